// round 3
// baseline (speedup 1.0000x reference)
#include <cuda_runtime.h>
#include <math.h>

// ---------------------------------------------------------------------------
// Constants: B=4, N=8192, DIM=512, HEADS=8, DH=64, M=256 landmarks, l=32
// ---------------------------------------------------------------------------
#define BB 4
#define NN 8192
#define DD 512
#define HH 8
#define DH 64
#define MM 256
#define BH 32
#define KS 16   /* k-split for attn3@v */

// ---------------------------------------------------------------------------
// Scratch (device globals; allocation is forbidden)
// ---------------------------------------------------------------------------
__device__ __align__(16) float g_xn  [(size_t)BB*NN*DD];
__device__ __align__(16) float g_q   [(size_t)BH*NN*DH];
__device__ __align__(16) float g_k   [(size_t)BH*NN*DH];
__device__ __align__(16) float g_v   [(size_t)BH*NN*DH];
__device__ __align__(16) float g_ql  [(size_t)BH*MM*DH];
__device__ __align__(16) float g_kl  [(size_t)BH*MM*DH];
__device__ __align__(16) float g_attn2[(size_t)BH*MM*MM];
__device__ __align__(16) float g_z   [(size_t)BH*MM*MM];
__device__ __align__(16) float g_z2  [(size_t)BH*MM*MM];
__device__ __align__(16) float g_xz  [(size_t)BH*MM*MM];
__device__ __align__(16) float g_t   [(size_t)BH*MM*MM];
__device__ __align__(16) float g_u   [(size_t)BH*MM*MM];
__device__ __align__(16) float g_sim3[(size_t)BH*MM*NN];
__device__ __align__(16) float g_p3  [(size_t)BH*KS*MM*DH];
__device__ __align__(16) float g_out3[(size_t)BH*MM*DH];
__device__ __align__(16) float g_wc  [(size_t)BH*MM*DH];
__device__ __align__(16) float g_y   [(size_t)BB*NN*DD];
__device__ int g_maxA;
__device__ int g_maxB;

// ---------------------------------------------------------------------------
// LayerNorm: one block per row (512), 128 threads, float4
// ---------------------------------------------------------------------------
__global__ __launch_bounds__(128) void ln_kernel(const float* __restrict__ x,
                                                 const float* __restrict__ w,
                                                 const float* __restrict__ bia) {
    int row = blockIdx.x, tid = threadIdx.x;
    const float4* xr = reinterpret_cast<const float4*>(x + (size_t)row * DD);
    float4 v = xr[tid];
    float s  = v.x + v.y + v.z + v.w;
    float sq = v.x*v.x + v.y*v.y + v.z*v.z + v.w*v.w;
    __shared__ float sm[4], sm2[4];
    #pragma unroll
    for (int o = 16; o > 0; o >>= 1) {
        s  += __shfl_down_sync(0xffffffffu, s,  o);
        sq += __shfl_down_sync(0xffffffffu, sq, o);
    }
    if ((tid & 31) == 0) { sm[tid >> 5] = s; sm2[tid >> 5] = sq; }
    __syncthreads();
    if (tid == 0) {
        float a = 0.f, b2 = 0.f;
        #pragma unroll
        for (int i = 0; i < 4; i++) { a += sm[i]; b2 += sm2[i]; }
        sm[0] = a; sm2[0] = b2;
    }
    __syncthreads();
    float mean = sm[0] * (1.f / 512.f);
    float var  = sm2[0] * (1.f / 512.f) - mean * mean;
    float rstd = rsqrtf(var + 1e-5f);
    float4 wv = reinterpret_cast<const float4*>(w)[tid];
    float4 bv = reinterpret_cast<const float4*>(bia)[tid];
    float4 o;
    o.x = (v.x - mean) * rstd * wv.x + bv.x;
    o.y = (v.y - mean) * rstd * wv.y + bv.y;
    o.z = (v.z - mean) * rstd * wv.z + bv.z;
    o.w = (v.w - mean) * rstd * wv.w + bv.w;
    reinterpret_cast<float4*>(g_xn + (size_t)row * DD)[tid] = o;
}

// ---------------------------------------------------------------------------
// QKV GEMM: (32768x512)@(512x1536) -> head-major q(*0.125)/k/v
// 128x128 tile, BK=16, 256 thr, 8x8 micro
// ---------------------------------------------------------------------------
__global__ __launch_bounds__(256) void gemm_qkv(const float* __restrict__ Wm) {
    __shared__ float As[16][132];
    __shared__ float Bs[16][132];
    int tid = threadIdx.x;
    int bn = blockIdx.x, bm = blockIdx.y;
    int tx = tid & 15, ty = tid >> 4;
    const float* Ab = g_xn + (size_t)bm * 128 * DD;
    float acc[8][8] = {};
    for (int kk = 0; kk < 512; kk += 16) {
        #pragma unroll
        for (int u = 0; u < 2; u++) {
            int g = u * 256 + tid;
            int m = g >> 2, k4 = g & 3;
            float4 av = *reinterpret_cast<const float4*>(Ab + (size_t)m * 512 + kk + k4 * 4);
            As[k4*4+0][m] = av.x; As[k4*4+1][m] = av.y;
            As[k4*4+2][m] = av.z; As[k4*4+3][m] = av.w;
        }
        #pragma unroll
        for (int u = 0; u < 2; u++) {
            int g = u * 256 + tid;
            int k = g >> 5, n4 = g & 31;
            *reinterpret_cast<float4*>(&Bs[k][n4*4]) =
                *reinterpret_cast<const float4*>(Wm + (size_t)(kk + k) * 1536 + bn * 128 + n4 * 4);
        }
        __syncthreads();
        #pragma unroll
        for (int k = 0; k < 16; k++) {
            float a[8], b[8];
            *(float4*)&a[0] = *(const float4*)&As[k][ty*8];
            *(float4*)&a[4] = *(const float4*)&As[k][ty*8+4];
            *(float4*)&b[0] = *(const float4*)&Bs[k][tx*8];
            *(float4*)&b[4] = *(const float4*)&Bs[k][tx*8+4];
            #pragma unroll
            for (int i = 0; i < 8; i++)
                #pragma unroll
                for (int j = 0; j < 8; j++)
                    acc[i][j] += a[i] * b[j];
        }
        __syncthreads();
    }
    #pragma unroll
    for (int i = 0; i < 8; i++) {
        int row = bm * 128 + ty * 8 + i;
        int bq = row >> 13, n = row & (NN - 1);
        #pragma unroll
        for (int jj = 0; jj < 2; jj++) {
            int col = bn * 128 + tx * 8 + jj * 4;
            int which = col >> 9, inner = col & 511;
            int h = inner >> 6, d = inner & 63;
            float4 v = make_float4(acc[i][jj*4+0], acc[i][jj*4+1],
                                   acc[i][jj*4+2], acc[i][jj*4+3]);
            if (which == 0) { v.x *= 0.125f; v.y *= 0.125f; v.z *= 0.125f; v.w *= 0.125f; }
            float* dst = which == 0 ? g_q : (which == 1 ? g_k : g_v);
            *reinterpret_cast<float4*>(dst + (((size_t)(bq * HH + h)) * NN + n) * DH + d) = v;
        }
    }
}

// ---------------------------------------------------------------------------
// Landmarks: mean over 32-token chunks
// ---------------------------------------------------------------------------
__global__ void landmark_kernel() {
    int m = blockIdx.x, bh = blockIdx.y;
    int d = threadIdx.x;
    size_t base = ((size_t)bh * NN + (size_t)m * 32) * DH + d;
    float sq = 0.f, sk = 0.f;
    #pragma unroll
    for (int j = 0; j < 32; j++) {
        sq += g_q[base + (size_t)j * DH];
        sk += g_k[base + (size_t)j * DH];
    }
    size_t o = ((size_t)bh * MM + m) * DH + d;
    g_ql[o] = sq * (1.f / 32.f);
    g_kl[o] = sk * (1.f / 32.f);
}

// ---------------------------------------------------------------------------
// NT GEMM (scores): C[bh,m,n] = sum_d A[bh,m,d]*B[bh,n,d], K=64, 128x128 tile
// MODE 0: sim2 (B=g_kl -> g_attn2); MODE 1: sim3 (B=g_k -> g_sim3)
// ---------------------------------------------------------------------------
template<int MODE>
__global__ __launch_bounds__(256) void gemm_nt() {
    constexpr int NR = MODE ? NN : MM;
    const float* Bm = MODE ? g_k : g_kl;
    float* C        = MODE ? g_sim3 : g_attn2;
    __shared__ float As[32][132];
    __shared__ float Bs[32][132];
    int bh = blockIdx.z;
    int n0 = blockIdx.x * 128, m0 = blockIdx.y * 128;
    const float* Ab = g_ql + ((size_t)bh * MM + m0) * DH;
    const float* Bb = Bm   + ((size_t)bh * NR + n0) * DH;
    float* Cb = C + (size_t)bh * MM * NR;
    int tid = threadIdx.x;
    int tx = tid & 15, ty = tid >> 4;
    float acc[8][8] = {};
    for (int kk = 0; kk < 64; kk += 32) {
        #pragma unroll
        for (int u = 0; u < 4; u++) {
            int g = u * 256 + tid;
            int m = g >> 3, k4 = g & 7;
            float4 av = *(const float4*)(Ab + (size_t)m * DH + kk + k4 * 4);
            As[k4*4+0][m] = av.x; As[k4*4+1][m] = av.y;
            As[k4*4+2][m] = av.z; As[k4*4+3][m] = av.w;
        }
        #pragma unroll
        for (int u = 0; u < 4; u++) {
            int g = u * 256 + tid;
            int m = g >> 3, k4 = g & 7;
            float4 bv = *(const float4*)(Bb + (size_t)m * DH + kk + k4 * 4);
            Bs[k4*4+0][m] = bv.x; Bs[k4*4+1][m] = bv.y;
            Bs[k4*4+2][m] = bv.z; Bs[k4*4+3][m] = bv.w;
        }
        __syncthreads();
        #pragma unroll
        for (int k = 0; k < 32; k++) {
            float a[8], b[8];
            *(float4*)&a[0] = *(const float4*)&As[k][ty*8];
            *(float4*)&a[4] = *(const float4*)&As[k][ty*8+4];
            *(float4*)&b[0] = *(const float4*)&Bs[k][tx*8];
            *(float4*)&b[4] = *(const float4*)&Bs[k][tx*8+4];
            #pragma unroll
            for (int i = 0; i < 8; i++)
                #pragma unroll
                for (int j = 0; j < 8; j++)
                    acc[i][j] += a[i] * b[j];
        }
        __syncthreads();
    }
    #pragma unroll
    for (int i = 0; i < 8; i++) {
        size_t r = (size_t)(m0 + ty * 8 + i) * NR + n0 + tx * 8;
        *(float4*)(Cb + r)     = make_float4(acc[i][0], acc[i][1], acc[i][2], acc[i][3]);
        *(float4*)(Cb + r + 4) = make_float4(acc[i][4], acc[i][5], acc[i][6], acc[i][7]);
    }
}

// ---------------------------------------------------------------------------
// Softmax over 256-wide rows (attn2), in place
// ---------------------------------------------------------------------------
__global__ __launch_bounds__(256) void softmax256() {
    int row = blockIdx.x, tid = threadIdx.x;
    float* p = g_attn2 + (size_t)row * MM;
    float v = p[tid];
    __shared__ float red[8];
    float m = v;
    #pragma unroll
    for (int o = 16; o; o >>= 1) m = fmaxf(m, __shfl_xor_sync(~0u, m, o));
    if ((tid & 31) == 0) red[tid >> 5] = m;
    __syncthreads();
    if (tid < 32) {
        float t = (tid < 8) ? red[tid] : -1e30f;
        #pragma unroll
        for (int o = 4; o; o >>= 1) t = fmaxf(t, __shfl_xor_sync(~0u, t, o));
        if (tid == 0) red[0] = t;
    }
    __syncthreads();
    float mx = red[0];
    __syncthreads();
    float e = __expf(v - mx);
    float s = e;
    #pragma unroll
    for (int o = 16; o; o >>= 1) s += __shfl_xor_sync(~0u, s, o);
    if ((tid & 31) == 0) red[tid >> 5] = s;
    __syncthreads();
    if (tid < 32) {
        float t = (tid < 8) ? red[tid] : 0.f;
        #pragma unroll
        for (int o = 4; o; o >>= 1) t += __shfl_xor_sync(~0u, t, o);
        if (tid == 0) red[0] = t;
    }
    __syncthreads();
    p[tid] = e / red[0];
}

// ---------------------------------------------------------------------------
// Softmax over 8192-wide rows (sim3), in place; 32 vals/thread in regs
// ---------------------------------------------------------------------------
__global__ __launch_bounds__(256) void softmax8192() {
    int row = blockIdx.x, tid = threadIdx.x;
    float4* p = (float4*)(g_sim3 + (size_t)row * NN);
    float4 v[8];
    float mx = -1e30f;
    #pragma unroll
    for (int i = 0; i < 8; i++) {
        v[i] = p[tid + i * 256];
        mx = fmaxf(mx, fmaxf(fmaxf(v[i].x, v[i].y), fmaxf(v[i].z, v[i].w)));
    }
    __shared__ float red[8];
    #pragma unroll
    for (int o = 16; o; o >>= 1) mx = fmaxf(mx, __shfl_xor_sync(~0u, mx, o));
    if ((tid & 31) == 0) red[tid >> 5] = mx;
    __syncthreads();
    if (tid < 32) {
        float t = (tid < 8) ? red[tid] : -1e30f;
        #pragma unroll
        for (int o = 4; o; o >>= 1) t = fmaxf(t, __shfl_xor_sync(~0u, t, o));
        if (tid == 0) red[0] = t;
    }
    __syncthreads();
    float MX = red[0];
    __syncthreads();
    float s = 0.f;
    #pragma unroll
    for (int i = 0; i < 8; i++) {
        v[i].x = __expf(v[i].x - MX); v[i].y = __expf(v[i].y - MX);
        v[i].z = __expf(v[i].z - MX); v[i].w = __expf(v[i].w - MX);
        s += v[i].x + v[i].y + v[i].z + v[i].w;
    }
    #pragma unroll
    for (int o = 16; o; o >>= 1) s += __shfl_xor_sync(~0u, s, o);
    if ((tid & 31) == 0) red[tid >> 5] = s;
    __syncthreads();
    if (tid < 32) {
        float t = (tid < 8) ? red[tid] : 0.f;
        #pragma unroll
        for (int o = 4; o; o >>= 1) t += __shfl_xor_sync(~0u, t, o);
        if (tid == 0) red[0] = t;
    }
    __syncthreads();
    float inv = 1.f / red[0];
    #pragma unroll
    for (int i = 0; i < 8; i++) {
        v[i].x *= inv; v[i].y *= inv; v[i].z *= inv; v[i].w *= inv;
        p[tid + i * 256] = v[i];
    }
}

// ---------------------------------------------------------------------------
// pinv init: global max |row sum| and |col sum| of attn2 (atomicMax on bits)
// ---------------------------------------------------------------------------
__global__ void init_max_kernel() { g_maxA = 0; g_maxB = 0; }

__global__ __launch_bounds__(256) void colrowmax_kernel() {
    int bh = blockIdx.x, tid = threadIdx.x;
    const float* a = g_attn2 + (size_t)bh * MM * MM;
    float cs = 0.f, rs = 0.f;
    for (int m = 0; m < MM; m++) cs += fabsf(a[(size_t)m * MM + tid]);
    for (int n = 0; n < MM; n++) rs += fabsf(a[(size_t)tid * MM + n]);
    __shared__ float r1[8], r2[8];
    #pragma unroll
    for (int o = 16; o; o >>= 1) {
        cs = fmaxf(cs, __shfl_xor_sync(~0u, cs, o));
        rs = fmaxf(rs, __shfl_xor_sync(~0u, rs, o));
    }
    if ((tid & 31) == 0) { r1[tid >> 5] = cs; r2[tid >> 5] = rs; }
    __syncthreads();
    if (tid == 0) {
        float a1 = r1[0], a2 = r2[0];
        #pragma unroll
        for (int i = 1; i < 8; i++) { a1 = fmaxf(a1, r1[i]); a2 = fmaxf(a2, r2[i]); }
        atomicMax(&g_maxA, __float_as_int(a1));
        atomicMax(&g_maxB, __float_as_int(a2));
    }
}

// z0 = attn2^T * (1/(maxA*maxB)), smem transpose
__global__ __launch_bounds__(256) void z0_kernel() {
    int bh = blockIdx.z;
    int c0 = blockIdx.x * 32, r0 = blockIdx.y * 32;
    int tid = threadIdx.x;
    __shared__ float t[32][33];
    const float* a = g_attn2 + (size_t)bh * MM * MM;
    #pragma unroll
    for (int rr = 0; rr < 4; rr++) {
        int r = rr * 8 + (tid >> 5), c = tid & 31;
        t[r][c] = a[(size_t)(r0 + r) * MM + c0 + c];
    }
    __syncthreads();
    float s = 1.f / (__int_as_float(g_maxA) * __int_as_float(g_maxB));
    float* z = g_z + (size_t)bh * MM * MM;
    #pragma unroll
    for (int rr = 0; rr < 4; rr++) {
        int r = rr * 8 + (tid >> 5), c = tid & 31;
        z[(size_t)(c0 + r) * MM + r0 + c] = t[c][r] * s;
    }
}

// ---------------------------------------------------------------------------
// Batched 256x256: C = alpha*(P@Q) + beta*R  (64x64 tile, BK=32, 4x4 micro)
// ---------------------------------------------------------------------------
__global__ __launch_bounds__(256) void matmul_ba(const float* __restrict__ P,
                                                 const float* __restrict__ Q,
                                                 const float* __restrict__ R,
                                                 float* __restrict__ C,
                                                 float alpha, float beta) {
    __shared__ float Ps[32][68];
    __shared__ float Qs[32][68];
    int bh = blockIdx.z;
    int m0 = blockIdx.y * 64, n0 = blockIdx.x * 64;
    size_t base = (size_t)bh * MM * MM;
    int tid = threadIdx.x;
    int tx = tid & 15, ty = tid >> 4;
    float acc[4][4] = {};
    for (int kk = 0; kk < 256; kk += 32) {
        #pragma unroll
        for (int u = 0; u < 2; u++) {
            int g = u * 256 + tid;
            int m = g >> 3, k4 = g & 7;
            float4 pv = *(const float4*)(P + base + (size_t)(m0 + m) * MM + kk + k4 * 4);
            Ps[k4*4+0][m] = pv.x; Ps[k4*4+1][m] = pv.y;
            Ps[k4*4+2][m] = pv.z; Ps[k4*4+3][m] = pv.w;
        }
        #pragma unroll
        for (int u = 0; u < 2; u++) {
            int g = u * 256 + tid;
            int k = g >> 4, n4 = g & 15;
            *(float4*)&Qs[k][n4*4] = *(const float4*)(Q + base + (size_t)(kk + k) * MM + n0 + n4 * 4);
        }
        __syncthreads();
        #pragma unroll
        for (int k = 0; k < 32; k++) {
            float a[4], b[4];
            *(float4*)a = *(const float4*)&Ps[k][ty*4];
            *(float4*)b = *(const float4*)&Qs[k][tx*4];
            #pragma unroll
            for (int i = 0; i < 4; i++)
                #pragma unroll
                for (int j = 0; j < 4; j++)
                    acc[i][j] += a[i] * b[j];
        }
        __syncthreads();
    }
    #pragma unroll
    for (int i = 0; i < 4; i++) {
        size_t off = base + (size_t)(m0 + ty * 4 + i) * MM + n0 + tx * 4;
        float4 rv = make_float4(0.f, 0.f, 0.f, 0.f);
        if (R) rv = *(const float4*)(R + off);
        float4 o;
        o.x = alpha * acc[i][0] + beta * rv.x;
        o.y = alpha * acc[i][1] + beta * rv.y;
        o.z = alpha * acc[i][2] + beta * rv.z;
        o.w = alpha * acc[i][3] + beta * rv.w;
        *(float4*)(C + off) = o;
    }
}

// ---------------------------------------------------------------------------
// attn3@v with k-split: partial C[bh,ks][64x64 tile] over 512-deep K chunk
// ---------------------------------------------------------------------------
__global__ __launch_bounds__(256) void pv_gemm() {
    __shared__ float As[32][68];
    __shared__ float Vs[32][68];
    int mt = blockIdx.x, ks = blockIdx.y, bh = blockIdx.z;
    int m0 = mt * 64, koff = ks * 512;
    const float* A = g_sim3 + (size_t)bh * MM * NN;
    const float* V = g_v + (size_t)bh * NN * DH;
    int tid = threadIdx.x;
    int tx = tid & 15, ty = tid >> 4;
    float acc[4][4] = {};
    for (int kk = 0; kk < 512; kk += 32) {
        #pragma unroll
        for (int u = 0; u < 2; u++) {
            int g = u * 256 + tid;
            int m = g >> 3, k4 = g & 7;
            float4 pv = *(const float4*)(A + (size_t)(m0 + m) * NN + koff + kk + k4 * 4);
            As[k4*4+0][m] = pv.x; As[k4*4+1][m] = pv.y;
            As[k4*4+2][m] = pv.z; As[k4*4+3][m] = pv.w;
        }
        #pragma unroll
        for (int u = 0; u < 2; u++) {
            int g = u * 256 + tid;
            int k = g >> 4, n4 = g & 15;
            *(float4*)&Vs[k][n4*4] = *(const float4*)(V + (size_t)(koff + kk + k) * DH + n4 * 4);
        }
        __syncthreads();
        #pragma unroll
        for (int k = 0; k < 32; k++) {
            float a[4], b[4];
            *(float4*)a = *(const float4*)&As[k][ty*4];
            *(float4*)b = *(const float4*)&Vs[k][tx*4];
            #pragma unroll
            for (int i = 0; i < 4; i++)
                #pragma unroll
                for (int j = 0; j < 4; j++)
                    acc[i][j] += a[i] * b[j];
        }
        __syncthreads();
    }
    #pragma unroll
    for (int i = 0; i < 4; i++) {
        size_t off = (((size_t)bh * KS + ks) * MM + m0 + ty * 4 + i) * DH + tx * 4;
        *(float4*)(g_p3 + off) = make_float4(acc[i][0], acc[i][1], acc[i][2], acc[i][3]);
    }
}

__global__ __launch_bounds__(256) void reduce_p3() {
    size_t t = (size_t)blockIdx.x * 256 + threadIdx.x;   // 32*256*64 = 524288
    size_t bh = t >> 14, rem = t & 16383;
    float s = 0.f;
    #pragma unroll
    for (int ks = 0; ks < KS; ks++)
        s += g_p3[((bh * KS + ks) << 14) + rem];
    g_out3[t] = s;
}

// ---------------------------------------------------------------------------
// Wc = z_final @ out3 : (256x256)@(256x64) per bh
// ---------------------------------------------------------------------------
__global__ __launch_bounds__(256) void matmul_small(const float* __restrict__ Z) {
    __shared__ float Ps[32][68];
    __shared__ float Qs[32][68];
    int mt = blockIdx.x, bh = blockIdx.y;
    int m0 = mt * 64;
    const float* A = Z + (size_t)bh * MM * MM;
    const float* Bm = g_out3 + (size_t)bh * MM * DH;
    int tid = threadIdx.x;
    int tx = tid & 15, ty = tid >> 4;
    float acc[4][4] = {};
    for (int kk = 0; kk < 256; kk += 32) {
        #pragma unroll
        for (int u = 0; u < 2; u++) {
            int g = u * 256 + tid;
            int m = g >> 3, k4 = g & 7;
            float4 pv = *(const float4*)(A + (size_t)(m0 + m) * MM + kk + k4 * 4);
            Ps[k4*4+0][m] = pv.x; Ps[k4*4+1][m] = pv.y;
            Ps[k4*4+2][m] = pv.z; Ps[k4*4+3][m] = pv.w;
        }
        #pragma unroll
        for (int u = 0; u < 2; u++) {
            int g = u * 256 + tid;
            int k = g >> 4, n4 = g & 15;
            *(float4*)&Qs[k][n4*4] = *(const float4*)(Bm + (size_t)(kk + k) * DH + n4 * 4);
        }
        __syncthreads();
        #pragma unroll
        for (int k = 0; k < 32; k++) {
            float a[4], b[4];
            *(float4*)a = *(const float4*)&Ps[k][ty*4];
            *(float4*)b = *(const float4*)&Qs[k][tx*4];
            #pragma unroll
            for (int i = 0; i < 4; i++)
                #pragma unroll
                for (int j = 0; j < 4; j++)
                    acc[i][j] += a[i] * b[j];
        }
        __syncthreads();
    }
    #pragma unroll
    for (int i = 0; i < 4; i++) {
        size_t off = ((size_t)bh * MM + m0 + ty * 4 + i) * DH + tx * 4;
        *(float4*)(g_wc + off) = make_float4(acc[i][0], acc[i][1], acc[i][2], acc[i][3]);
    }
}

// ---------------------------------------------------------------------------
// Depthwise conv-33 residual of v -> y[b,n,h*64+d]
// ---------------------------------------------------------------------------
__global__ __launch_bounds__(256) void conv_kernel(const float* __restrict__ res_w) {
    __shared__ float sv[160][64];
    __shared__ float sw[33];
    int bh = blockIdx.y, n0 = blockIdx.x * 128;
    int b = bh >> 3, h = bh & 7;
    int tid = threadIdx.x;
    if (tid < 33) sw[tid] = res_w[h * 33 + tid];
    const float* vb = g_v + (size_t)bh * NN * DH;
    #pragma unroll
    for (int i = 0; i < 10; i++) {
        int idx = tid + i * 256;              // over 2560 float4
        int r = idx >> 4, c4 = idx & 15;
        int tok = n0 - 16 + r;
        float4 val = make_float4(0.f, 0.f, 0.f, 0.f);
        if (tok >= 0 && tok < NN)
            val = *(const float4*)(vb + (size_t)tok * DH + c4 * 4);
        *(float4*)&sv[r][c4 * 4] = val;
    }
    __syncthreads();
    #pragma unroll
    for (int i = 0; i < 8; i++) {
        int idx = tid + i * 256;              // over 2048 items (128 n x 16 d4)
        int nl = idx >> 4, dg = idx & 15;
        float4 acc = make_float4(0.f, 0.f, 0.f, 0.f);
        #pragma unroll
        for (int j = 0; j < 33; j++) {
            float w = sw[j];
            float4 vv = *(const float4*)&sv[nl + j][dg * 4];
            acc.x += w * vv.x; acc.y += w * vv.y;
            acc.z += w * vv.z; acc.w += w * vv.w;
        }
        *(float4*)(g_y + ((size_t)b * NN + n0 + nl) * DD + h * 64 + dg * 4) = acc;
    }
}

// ---------------------------------------------------------------------------
// Fused attn1 path: y += softmax(q@kl^T) @ Wc, token-per-thread online softmax
// smem: kl (64KB) + Wc (64KB)
// ---------------------------------------------------------------------------
__global__ __launch_bounds__(256) void attn1_kernel() {
    extern __shared__ float sm[];
    float* kl = sm;                  // 256*64
    float* wc = sm + MM * DH;        // 256*64
    int bh = blockIdx.y;
    int b = bh >> 3, h = bh & 7;
    int tid = threadIdx.x;
    const float4* skl = (const float4*)(g_kl + (size_t)bh * MM * DH);
    const float4* swc = (const float4*)(g_wc + (size_t)bh * MM * DH);
    for (int i = tid; i < MM * DH / 4; i += 256) {
        ((float4*)kl)[i] = skl[i];
        ((float4*)wc)[i] = swc[i];
    }
    __syncthreads();
    int n = blockIdx.x * 256 + tid;
    const float4* qp = (const float4*)(g_q + ((size_t)bh * NN + n) * DH);
    float q[64];
    #pragma unroll
    for (int i = 0; i < 16; i++) {
        float4 v = qp[i];
        q[4*i] = v.x; q[4*i+1] = v.y; q[4*i+2] = v.z; q[4*i+3] = v.w;
    }
    float acc[64];
    #pragma unroll
    for (int i = 0; i < 64; i++) acc[i] = 0.f;
    float mx = -1e30f, ssum = 0.f;
    for (int m = 0; m < MM; m++) {
        const float4* kv4 = (const float4*)(kl + m * DH);
        float s = 0.f;
        #pragma unroll
        for (int i = 0; i < 16; i++) {
            float4 kv = kv4[i];
            s += q[4*i] * kv.x + q[4*i+1] * kv.y + q[4*i+2] * kv.z + q[4*i+3] * kv.w;
        }
        float mnew = fmaxf(mx, s);
        float f  = __expf(mx - mnew);
        float cc = __expf(s - mnew);
        ssum = ssum * f + cc;
        if (f != 1.f) {
            #pragma unroll
            for (int i = 0; i < 64; i++) acc[i] *= f;
        }
        mx = mnew;
        const float4* wv4 = (const float4*)(wc + m * DH);
        #pragma unroll
        for (int i = 0; i < 16; i++) {
            float4 wv = wv4[i];
            acc[4*i]   += cc * wv.x; acc[4*i+1] += cc * wv.y;
            acc[4*i+2] += cc * wv.z; acc[4*i+3] += cc * wv.w;
        }
    }
    float inv = 1.f / ssum;
    float* yp = g_y + ((size_t)b * NN + n) * DD + h * 64;
    #pragma unroll
    for (int i = 0; i < 16; i++) {
        float4 o = ((float4*)yp)[i];
        o.x += acc[4*i]   * inv; o.y += acc[4*i+1] * inv;
        o.z += acc[4*i+2] * inv; o.w += acc[4*i+3] * inv;
        ((float4*)yp)[i] = o;
    }
}

// ---------------------------------------------------------------------------
// Final GEMM: out = y @ w_out + b_out + x   (32768x512)@(512x512)
// ---------------------------------------------------------------------------
__global__ __launch_bounds__(256) void gemm_out(const float* __restrict__ Wm,
                                                const float* __restrict__ bo,
                                                const float* __restrict__ x,
                                                float* __restrict__ out) {
    __shared__ float As[16][132];
    __shared__ float Bs[16][132];
    int tid = threadIdx.x;
    int bn = blockIdx.x, bm = blockIdx.y;
    int tx = tid & 15, ty = tid >> 4;
    const float* Ab = g_y + (size_t)bm * 128 * DD;
    float acc[8][8] = {};
    for (int kk = 0; kk < 512; kk += 16) {
        #pragma unroll
        for (int u = 0; u < 2; u++) {
            int g = u * 256 + tid;
            int m = g >> 2, k4 = g & 3;
            float4 av = *(const float4*)(Ab + (size_t)m * 512 + kk + k4 * 4);
            As[k4*4+0][m] = av.x; As[k4*4+1][m] = av.y;
            As[k4*4+2][m] = av.z; As[k4*4+3][m] = av.w;
        }
        #pragma unroll
        for (int u = 0; u < 2; u++) {
            int g = u * 256 + tid;
            int k = g >> 5, n4 = g & 31;
            *(float4*)&Bs[k][n4*4] =
                *(const float4*)(Wm + (size_t)(kk + k) * 512 + bn * 128 + n4 * 4);
        }
        __syncthreads();
        #pragma unroll
        for (int k = 0; k < 16; k++) {
            float a[8], b[8];
            *(float4*)&a[0] = *(const float4*)&As[k][ty*8];
            *(float4*)&a[4] = *(const float4*)&As[k][ty*8+4];
            *(float4*)&b[0] = *(const float4*)&Bs[k][tx*8];
            *(float4*)&b[4] = *(const float4*)&Bs[k][tx*8+4];
            #pragma unroll
            for (int i = 0; i < 8; i++)
                #pragma unroll
                for (int j = 0; j < 8; j++)
                    acc[i][j] += a[i] * b[j];
        }
        __syncthreads();
    }
    #pragma unroll
    for (int i = 0; i < 8; i++) {
        size_t row = (size_t)bm * 128 + ty * 8 + i;
        #pragma unroll
        for (int jj = 0; jj < 2; jj++) {
            int col = bn * 128 + tx * 8 + jj * 4;
            float4 bv = *(const float4*)(bo + col);
            float4 xv = *(const float4*)(x + row * 512 + col);
            float4 o;
            o.x = acc[i][jj*4+0] + bv.x + xv.x;
            o.y = acc[i][jj*4+1] + bv.y + xv.y;
            o.z = acc[i][jj*4+2] + bv.z + xv.z;
            o.w = acc[i][jj*4+3] + bv.w + xv.w;
            *(float4*)(out + row * 512 + col) = o;
        }
    }
}

// ---------------------------------------------------------------------------
// Launch
// ---------------------------------------------------------------------------
extern "C" void kernel_launch(void* const* d_in, const int* in_sizes, int n_in,
                              void* d_out, int out_size) {
    const float* x     = (const float*)d_in[0];
    const float* ln_w  = (const float*)d_in[1];
    const float* ln_b  = (const float*)d_in[2];
    const float* w_qkv = (const float*)d_in[3];
    const float* w_out = (const float*)d_in[4];
    const float* b_out = (const float*)d_in[5];
    const float* res_w = (const float*)d_in[6];
    float* out = (float*)d_out;

    float *p_attn2, *p_z, *p_z2, *p_xz, *p_t, *p_u;
    cudaGetSymbolAddress((void**)&p_attn2, g_attn2);
    cudaGetSymbolAddress((void**)&p_z,  g_z);
    cudaGetSymbolAddress((void**)&p_z2, g_z2);
    cudaGetSymbolAddress((void**)&p_xz, g_xz);
    cudaGetSymbolAddress((void**)&p_t,  g_t);
    cudaGetSymbolAddress((void**)&p_u,  g_u);

    cudaFuncSetAttribute(attn1_kernel,
                         cudaFuncAttributeMaxDynamicSharedMemorySize, 131072);

    ln_kernel<<<BB * NN, 128>>>(x, ln_w, ln_b);
    gemm_qkv<<<dim3(12, 256), 256>>>(w_qkv);
    landmark_kernel<<<dim3(MM, BH), 64>>>();
    gemm_nt<0><<<dim3(2, 2, BH), 256>>>();     // sim2
    gemm_nt<1><<<dim3(64, 2, BH), 256>>>();    // sim3
    softmax256<<<BH * MM, 256>>>();            // attn2
    softmax8192<<<BH * MM, 256>>>();           // attn3 in g_sim3
    init_max_kernel<<<1, 1>>>();
    colrowmax_kernel<<<BH, 256>>>();
    z0_kernel<<<dim3(8, 8, BH), 256>>>();

    dim3 gba(4, 4, BH);
    float *zc = p_z, *zn = p_z2;
    for (int it = 0; it < 6; it++) {
        matmul_ba<<<gba, 256>>>(p_attn2, zc, nullptr, p_xz, 1.f, 0.f);   // A = x@z
        matmul_ba<<<gba, 256>>>(p_xz, p_xz, p_xz, p_t, -1.f, 7.f);       // t = 7A - A^2
        matmul_ba<<<gba, 256>>>(p_xz, p_t, p_xz, p_u, -1.f, 15.f);       // u = 15A - A@t
        matmul_ba<<<gba, 256>>>(zc, p_u, zc, zn, -0.25f, 3.25f);         // z' = 3.25z - .25 z@u
        float* tmp = zc; zc = zn; zn = tmp;
    }

    pv_gemm<<<dim3(4, KS, BH), 256>>>();
    reduce_p3<<<2048, 256>>>();
    matmul_small<<<dim3(4, BH), 256>>>(zc);    // Wc = z_final @ out3
    conv_kernel<<<dim3(64, BH), 256>>>(res_w); // y = conv residual
    attn1_kernel<<<dim3(32, BH), 256, 131072>>>(); // y += attn1 @ Wc
    gemm_out<<<dim3(4, 256), 256>>>(w_out, b_out, x, out);
}

// round 5
// speedup vs baseline: 1.6087x; 1.6087x over previous
#include <cuda_runtime.h>
#include <stdint.h>
#include <math.h>

// ---------------------------------------------------------------------------
// Constants: B=4, N=8192, DIM=512, HEADS=8, DH=64, M=256 landmarks, l=32
// ---------------------------------------------------------------------------
#define BB 4
#define NN 8192
#define DD 512
#define HH 8
#define DH 64
#define MM 256
#define BH 32
#define KS 16   /* k-split for attn3@v */

// ---------------------------------------------------------------------------
// Scratch (device globals; allocation is forbidden)
// ---------------------------------------------------------------------------
__device__ __align__(16) float g_xn  [(size_t)BB*NN*DD];
__device__ __align__(16) float g_q   [(size_t)BH*NN*DH];
__device__ __align__(16) float g_k   [(size_t)BH*NN*DH];
__device__ __align__(16) float g_v   [(size_t)BH*NN*DH];
__device__ __align__(16) float g_ql  [(size_t)BH*MM*DH];
__device__ __align__(16) float g_kl  [(size_t)BH*MM*DH];
__device__ __align__(16) float g_attn2[(size_t)BH*MM*MM];
__device__ __align__(16) float g_z   [(size_t)BH*MM*MM];
__device__ __align__(16) float g_z2  [(size_t)BH*MM*MM];
__device__ __align__(16) float g_xz  [(size_t)BH*MM*MM];
__device__ __align__(16) float g_t   [(size_t)BH*MM*MM];
__device__ __align__(16) float g_u   [(size_t)BH*MM*MM];
__device__ __align__(16) float g_sim3[(size_t)BH*MM*NN];
__device__ __align__(16) float g_sim1[(size_t)BH*NN*MM];
__device__ __align__(16) float g_p3  [(size_t)BH*KS*MM*DH];
__device__ __align__(16) float g_out3[(size_t)BH*MM*DH];
__device__ __align__(16) float g_wc  [(size_t)BH*MM*DH];
__device__ __align__(16) float g_y   [(size_t)BB*NN*DD];
__device__ int g_maxA;
__device__ int g_maxB;

// ---------------------------------------------------------------------------
// TF32 helpers
// ---------------------------------------------------------------------------
__device__ __forceinline__ uint32_t f2tf(float f) {
    uint32_t u;
    asm("cvt.rna.tf32.f32 %0, %1;" : "=r"(u) : "f"(f));
    return u;
}

__device__ __forceinline__ void mma8(float* d, const uint32_t* a, const uint32_t* b) {
    asm volatile(
        "mma.sync.aligned.m16n8k8.row.col.f32.tf32.tf32.f32 "
        "{%0,%1,%2,%3}, {%4,%5,%6,%7}, {%8,%9}, {%0,%1,%2,%3};"
        : "+f"(d[0]), "+f"(d[1]), "+f"(d[2]), "+f"(d[3])
        : "r"(a[0]), "r"(a[1]), "r"(a[2]), "r"(a[3]), "r"(b[0]), "r"(b[1]));
}

// ---------------------------------------------------------------------------
// Generic TF32 tensor-core GEMM, 256 thr, 8 warps (2m x 4n), BM x BN x BK tile
// EPI: 0=QKV scatter  1=out+bias+x  2=plain batched store  3=p3 partial
//      4=alpha*(PQ)+beta*R batched  5=y += (attn1@Wc) scatter
// TRB: B is [N,K] row-major (NT product) instead of [K,N]
// ---------------------------------------------------------------------------
template<int EPI, int BM, int BN, int BK, bool TRB>
__global__ __launch_bounds__(256) void tc_gemm(
    const float* __restrict__ A, const float* __restrict__ Bg,
    float* __restrict__ C, const float* __restrict__ X1, const float* __restrict__ X2,
    int N, int K, int lda, int ldb,
    long long bsA, long long bsB, long long bsC,
    float alpha, float beta)
{
    constexpr int PA = BM + 8, PB = BN + 8;
    constexpr int MT = (BM / 2) / 16;
    constexpr int NT = (BN / 4) / 8;
    __shared__ uint32_t As[BK][PA];
    __shared__ uint32_t Bs[BK][PB];

    int tid = threadIdx.x, lane = tid & 31, warp = tid >> 5;
    int wm0 = (warp >> 2) * (BM / 2);
    int wn0 = (warp & 3) * (BN / 4);
    int z = blockIdx.z;
    int m0 = blockIdx.y * BM, n0 = blockIdx.x * BN;

    const float* Ab;
    const float* Bb;
    if constexpr (EPI == 3) {
        int bh = z >> 4, ks = z & 15;
        Ab = A  + (size_t)bh * MM * NN + (size_t)ks * 512;
        Bb = Bg + (size_t)bh * NN * DH + (size_t)ks * 512 * DH;
    } else {
        Ab = A  + (size_t)z * bsA;
        Bb = Bg + (size_t)z * bsB;
    }

    float acc[MT][NT][4];
    #pragma unroll
    for (int i = 0; i < MT; i++)
        #pragma unroll
        for (int j = 0; j < NT; j++)
            #pragma unroll
            for (int r = 0; r < 4; r++) acc[i][j][r] = 0.f;

    for (int k0 = 0; k0 < K; k0 += BK) {
        // ---- load A tile (BM x BK), row-major source, f4 along k
        #pragma unroll
        for (int c = 0; c < (BM * BK) / 1024; c++) {
            int id = c * 256 + tid;
            int m  = id / (BK / 4);
            int kq = id % (BK / 4);
            float4 v = *(const float4*)(Ab + (size_t)(m0 + m) * lda + k0 + kq * 4);
            As[kq*4+0][m] = f2tf(v.x); As[kq*4+1][m] = f2tf(v.y);
            As[kq*4+2][m] = f2tf(v.z); As[kq*4+3][m] = f2tf(v.w);
        }
        // ---- load B tile
        if constexpr (!TRB) {
            #pragma unroll
            for (int c = 0; c < (BK * BN) / 1024; c++) {
                int id = c * 256 + tid;
                int k  = id / (BN / 4);
                int nq = id % (BN / 4);
                float4 v = *(const float4*)(Bb + (size_t)(k0 + k) * ldb + n0 + nq * 4);
                Bs[k][nq*4+0] = f2tf(v.x); Bs[k][nq*4+1] = f2tf(v.y);
                Bs[k][nq*4+2] = f2tf(v.z); Bs[k][nq*4+3] = f2tf(v.w);
            }
        } else {
            #pragma unroll
            for (int c = 0; c < (BN * BK) / 1024; c++) {
                int id = c * 256 + tid;
                int n  = id / (BK / 4);
                int kq = id % (BK / 4);
                float4 v = *(const float4*)(Bb + (size_t)(n0 + n) * ldb + k0 + kq * 4);
                Bs[kq*4+0][n] = f2tf(v.x); Bs[kq*4+1][n] = f2tf(v.y);
                Bs[kq*4+2][n] = f2tf(v.z); Bs[kq*4+3][n] = f2tf(v.w);
            }
        }
        __syncthreads();
        #pragma unroll
        for (int ks = 0; ks < BK / 8; ks++) {
            uint32_t af[MT][4], bf[NT][2];
            int kr = ks * 8 + (lane & 3);
            int mr = wm0 + (lane >> 2);
            #pragma unroll
            for (int mt = 0; mt < MT; mt++) {
                af[mt][0] = As[kr    ][mr + mt * 16];
                af[mt][1] = As[kr    ][mr + mt * 16 + 8];
                af[mt][2] = As[kr + 4][mr + mt * 16];
                af[mt][3] = As[kr + 4][mr + mt * 16 + 8];
            }
            int nr = wn0 + (lane >> 2);
            #pragma unroll
            for (int nt = 0; nt < NT; nt++) {
                bf[nt][0] = Bs[kr    ][nr + nt * 8];
                bf[nt][1] = Bs[kr + 4][nr + nt * 8];
            }
            #pragma unroll
            for (int mt = 0; mt < MT; mt++)
                #pragma unroll
                for (int nt = 0; nt < NT; nt++)
                    mma8(acc[mt][nt], af[mt], bf[nt]);
        }
        __syncthreads();
    }

    // ---- epilogue
    #pragma unroll
    for (int mt = 0; mt < MT; mt++) {
        #pragma unroll
        for (int nt = 0; nt < NT; nt++) {
            int row = m0 + wm0 + mt * 16 + (lane >> 2);
            int col = n0 + wn0 + nt * 8 + (lane & 3) * 2;
            float2 lo = make_float2(acc[mt][nt][0], acc[mt][nt][1]);
            float2 hi = make_float2(acc[mt][nt][2], acc[mt][nt][3]);
            if constexpr (EPI == 0) {
                int which = col >> 9, inner = col & 511;
                int h = inner >> 6, d = inner & 63;
                float* dst = which == 0 ? g_q : (which == 1 ? g_k : g_v);
                float s = (which == 0) ? 0.125f : 1.f;
                int bq = row >> 13, n = row & (NN - 1);
                *(float2*)(dst + (((size_t)(bq*HH+h))*NN + n    )*DH + d) = make_float2(lo.x*s, lo.y*s);
                *(float2*)(dst + (((size_t)(bq*HH+h))*NN + n + 8)*DH + d) = make_float2(hi.x*s, hi.y*s);
            } else if constexpr (EPI == 1) {
                float2 bv = *(const float2*)(X1 + col);
                size_t r1 = (size_t)row * DD + col, r2 = (size_t)(row + 8) * DD + col;
                float2 x1 = *(const float2*)(X2 + r1);
                float2 x2 = *(const float2*)(X2 + r2);
                *(float2*)(C + r1) = make_float2(lo.x + bv.x + x1.x, lo.y + bv.y + x1.y);
                *(float2*)(C + r2) = make_float2(hi.x + bv.x + x2.x, hi.y + bv.y + x2.y);
            } else if constexpr (EPI == 2) {
                size_t base = (size_t)z * bsC;
                *(float2*)(C + base + (size_t)row       * N + col) = lo;
                *(float2*)(C + base + (size_t)(row + 8) * N + col) = hi;
            } else if constexpr (EPI == 3) {
                size_t base = (size_t)z * (MM * DH);
                *(float2*)(C + base + (row    ) * DH + col) = lo;
                *(float2*)(C + base + (row + 8) * DH + col) = hi;
            } else if constexpr (EPI == 4) {
                size_t base = (size_t)z * (MM * MM);
                size_t r1 = base + (size_t)row * MM + col;
                size_t r2 = base + (size_t)(row + 8) * MM + col;
                float2 rv1 = make_float2(0.f, 0.f), rv2 = make_float2(0.f, 0.f);
                if (beta != 0.f) {
                    rv1 = *(const float2*)(X1 + r1);
                    rv2 = *(const float2*)(X1 + r2);
                }
                *(float2*)(C + r1) = make_float2(alpha*lo.x + beta*rv1.x, alpha*lo.y + beta*rv1.y);
                *(float2*)(C + r2) = make_float2(alpha*hi.x + beta*rv2.x, alpha*hi.y + beta*rv2.y);
            } else if constexpr (EPI == 5) {
                int b = z >> 3, h = z & 7;
                size_t r1 = ((size_t)b * NN + row    ) * DD + h * 64 + col;
                size_t r2 = ((size_t)b * NN + row + 8) * DD + h * 64 + col;
                float2 y1 = *(float2*)(C + r1);
                float2 y2 = *(float2*)(C + r2);
                *(float2*)(C + r1) = make_float2(y1.x + lo.x, y1.y + lo.y);
                *(float2*)(C + r2) = make_float2(y2.x + hi.x, y2.y + hi.y);
            }
        }
    }
}

// ---------------------------------------------------------------------------
// LayerNorm: one block per row (512), 128 threads, float4
// ---------------------------------------------------------------------------
__global__ __launch_bounds__(128) void ln_kernel(const float* __restrict__ x,
                                                 const float* __restrict__ w,
                                                 const float* __restrict__ bia) {
    int row = blockIdx.x, tid = threadIdx.x;
    const float4* xr = reinterpret_cast<const float4*>(x + (size_t)row * DD);
    float4 v = xr[tid];
    float s  = v.x + v.y + v.z + v.w;
    float sq = v.x*v.x + v.y*v.y + v.z*v.z + v.w*v.w;
    __shared__ float sm[4], sm2[4];
    #pragma unroll
    for (int o = 16; o > 0; o >>= 1) {
        s  += __shfl_down_sync(0xffffffffu, s,  o);
        sq += __shfl_down_sync(0xffffffffu, sq, o);
    }
    if ((tid & 31) == 0) { sm[tid >> 5] = s; sm2[tid >> 5] = sq; }
    __syncthreads();
    if (tid == 0) {
        float a = 0.f, b2 = 0.f;
        #pragma unroll
        for (int i = 0; i < 4; i++) { a += sm[i]; b2 += sm2[i]; }
        sm[0] = a; sm2[0] = b2;
    }
    __syncthreads();
    float mean = sm[0] * (1.f / 512.f);
    float var  = sm2[0] * (1.f / 512.f) - mean * mean;
    float rstd = rsqrtf(var + 1e-5f);
    float4 wv = reinterpret_cast<const float4*>(w)[tid];
    float4 bv = reinterpret_cast<const float4*>(bia)[tid];
    float4 o;
    o.x = (v.x - mean) * rstd * wv.x + bv.x;
    o.y = (v.y - mean) * rstd * wv.y + bv.y;
    o.z = (v.z - mean) * rstd * wv.z + bv.z;
    o.w = (v.w - mean) * rstd * wv.w + bv.w;
    reinterpret_cast<float4*>(g_xn + (size_t)row * DD)[tid] = o;
}

// ---------------------------------------------------------------------------
// Landmarks: mean over 32-token chunks
// ---------------------------------------------------------------------------
__global__ void landmark_kernel() {
    int m = blockIdx.x, bh = blockIdx.y;
    int d = threadIdx.x;
    size_t base = ((size_t)bh * NN + (size_t)m * 32) * DH + d;
    float sq = 0.f, sk = 0.f;
    #pragma unroll
    for (int j = 0; j < 32; j++) {
        sq += g_q[base + (size_t)j * DH];
        sk += g_k[base + (size_t)j * DH];
    }
    size_t o = ((size_t)bh * MM + m) * DH + d;
    g_ql[o] = sq * (1.f / 32.f);
    g_kl[o] = sk * (1.f / 32.f);
}

// ---------------------------------------------------------------------------
// sim2 (FFMA fp32, kept for pinv conditioning): C[m,n] = ql . kl, K=64
// ---------------------------------------------------------------------------
__global__ __launch_bounds__(256) void gemm_sim2() {
    __shared__ float As[32][132];
    __shared__ float Bs[32][132];
    int bh = blockIdx.z;
    int n0 = blockIdx.x * 128, m0 = blockIdx.y * 128;
    const float* Ab = g_ql + ((size_t)bh * MM + m0) * DH;
    const float* Bb = g_kl + ((size_t)bh * MM + n0) * DH;
    float* Cb = g_attn2 + (size_t)bh * MM * MM;
    int tid = threadIdx.x;
    int tx = tid & 15, ty = tid >> 4;
    float acc[8][8] = {};
    for (int kk = 0; kk < 64; kk += 32) {
        #pragma unroll
        for (int u = 0; u < 4; u++) {
            int g = u * 256 + tid;
            int m = g >> 3, k4 = g & 7;
            float4 av = *(const float4*)(Ab + (size_t)m * DH + kk + k4 * 4);
            As[k4*4+0][m] = av.x; As[k4*4+1][m] = av.y;
            As[k4*4+2][m] = av.z; As[k4*4+3][m] = av.w;
        }
        #pragma unroll
        for (int u = 0; u < 4; u++) {
            int g = u * 256 + tid;
            int m = g >> 3, k4 = g & 7;
            float4 bv = *(const float4*)(Bb + (size_t)m * DH + kk + k4 * 4);
            Bs[k4*4+0][m] = bv.x; Bs[k4*4+1][m] = bv.y;
            Bs[k4*4+2][m] = bv.z; Bs[k4*4+3][m] = bv.w;
        }
        __syncthreads();
        #pragma unroll
        for (int k = 0; k < 32; k++) {
            float a[8], b[8];
            *(float4*)&a[0] = *(const float4*)&As[k][ty*8];
            *(float4*)&a[4] = *(const float4*)&As[k][ty*8+4];
            *(float4*)&b[0] = *(const float4*)&Bs[k][tx*8];
            *(float4*)&b[4] = *(const float4*)&Bs[k][tx*8+4];
            #pragma unroll
            for (int i = 0; i < 8; i++)
                #pragma unroll
                for (int j = 0; j < 8; j++)
                    acc[i][j] += a[i] * b[j];
        }
        __syncthreads();
    }
    #pragma unroll
    for (int i = 0; i < 8; i++) {
        size_t r = (size_t)(m0 + ty * 8 + i) * MM + n0 + tx * 8;
        *(float4*)(Cb + r)     = make_float4(acc[i][0], acc[i][1], acc[i][2], acc[i][3]);
        *(float4*)(Cb + r + 4) = make_float4(acc[i][4], acc[i][5], acc[i][6], acc[i][7]);
    }
}

// ---------------------------------------------------------------------------
// Softmax over 256-wide rows (attn2), one block per row
// ---------------------------------------------------------------------------
__global__ __launch_bounds__(256) void softmax256() {
    int row = blockIdx.x, tid = threadIdx.x;
    float* p = g_attn2 + (size_t)row * MM;
    float v = p[tid];
    __shared__ float red[8];
    float m = v;
    #pragma unroll
    for (int o = 16; o; o >>= 1) m = fmaxf(m, __shfl_xor_sync(~0u, m, o));
    if ((tid & 31) == 0) red[tid >> 5] = m;
    __syncthreads();
    if (tid < 32) {
        float t = (tid < 8) ? red[tid] : -1e30f;
        #pragma unroll
        for (int o = 4; o; o >>= 1) t = fmaxf(t, __shfl_xor_sync(~0u, t, o));
        if (tid == 0) red[0] = t;
    }
    __syncthreads();
    float mx = red[0];
    __syncthreads();
    float e = __expf(v - mx);
    float s = e;
    #pragma unroll
    for (int o = 16; o; o >>= 1) s += __shfl_xor_sync(~0u, s, o);
    if ((tid & 31) == 0) red[tid >> 5] = s;
    __syncthreads();
    if (tid < 32) {
        float t = (tid < 8) ? red[tid] : 0.f;
        #pragma unroll
        for (int o = 4; o; o >>= 1) t += __shfl_xor_sync(~0u, t, o);
        if (tid == 0) red[0] = t;
    }
    __syncthreads();
    p[tid] = e / red[0];
}

// ---------------------------------------------------------------------------
// Warp-per-row softmax over 256-wide rows (sim1): 8 rows/block
// ---------------------------------------------------------------------------
__global__ __launch_bounds__(256) void softmax256w(float* __restrict__ P) {
    int warp = threadIdx.x >> 5, lane = threadIdx.x & 31;
    size_t row = (size_t)blockIdx.x * 8 + warp;
    float4* p = (float4*)(P + row * 256);
    float4 v0 = p[lane], v1 = p[lane + 32];
    float mx = fmaxf(fmaxf(fmaxf(v0.x, v0.y), fmaxf(v0.z, v0.w)),
                     fmaxf(fmaxf(v1.x, v1.y), fmaxf(v1.z, v1.w)));
    #pragma unroll
    for (int o = 16; o; o >>= 1) mx = fmaxf(mx, __shfl_xor_sync(~0u, mx, o));
    v0.x = __expf(v0.x - mx); v0.y = __expf(v0.y - mx);
    v0.z = __expf(v0.z - mx); v0.w = __expf(v0.w - mx);
    v1.x = __expf(v1.x - mx); v1.y = __expf(v1.y - mx);
    v1.z = __expf(v1.z - mx); v1.w = __expf(v1.w - mx);
    float s = v0.x + v0.y + v0.z + v0.w + v1.x + v1.y + v1.z + v1.w;
    #pragma unroll
    for (int o = 16; o; o >>= 1) s += __shfl_xor_sync(~0u, s, o);
    float inv = 1.f / s;
    v0.x *= inv; v0.y *= inv; v0.z *= inv; v0.w *= inv;
    v1.x *= inv; v1.y *= inv; v1.z *= inv; v1.w *= inv;
    p[lane] = v0; p[lane + 32] = v1;
}

// ---------------------------------------------------------------------------
// Softmax over 8192-wide rows (sim3), in place; 32 vals/thread in regs
// ---------------------------------------------------------------------------
__global__ __launch_bounds__(256) void softmax8192() {
    int row = blockIdx.x, tid = threadIdx.x;
    float4* p = (float4*)(g_sim3 + (size_t)row * NN);
    float4 v[8];
    float mx = -1e30f;
    #pragma unroll
    for (int i = 0; i < 8; i++) {
        v[i] = p[tid + i * 256];
        mx = fmaxf(mx, fmaxf(fmaxf(v[i].x, v[i].y), fmaxf(v[i].z, v[i].w)));
    }
    __shared__ float red[8];
    #pragma unroll
    for (int o = 16; o; o >>= 1) mx = fmaxf(mx, __shfl_xor_sync(~0u, mx, o));
    if ((tid & 31) == 0) red[tid >> 5] = mx;
    __syncthreads();
    if (tid < 32) {
        float t = (tid < 8) ? red[tid] : -1e30f;
        #pragma unroll
        for (int o = 4; o; o >>= 1) t = fmaxf(t, __shfl_xor_sync(~0u, t, o));
        if (tid == 0) red[0] = t;
    }
    __syncthreads();
    float MX = red[0];
    __syncthreads();
    float s = 0.f;
    #pragma unroll
    for (int i = 0; i < 8; i++) {
        v[i].x = __expf(v[i].x - MX); v[i].y = __expf(v[i].y - MX);
        v[i].z = __expf(v[i].z - MX); v[i].w = __expf(v[i].w - MX);
        s += v[i].x + v[i].y + v[i].z + v[i].w;
    }
    #pragma unroll
    for (int o = 16; o; o >>= 1) s += __shfl_xor_sync(~0u, s, o);
    if ((tid & 31) == 0) red[tid >> 5] = s;
    __syncthreads();
    if (tid < 32) {
        float t = (tid < 8) ? red[tid] : 0.f;
        #pragma unroll
        for (int o = 4; o; o >>= 1) t += __shfl_xor_sync(~0u, t, o);
        if (tid == 0) red[0] = t;
    }
    __syncthreads();
    float inv = 1.f / red[0];
    #pragma unroll
    for (int i = 0; i < 8; i++) {
        v[i].x *= inv; v[i].y *= inv; v[i].z *= inv; v[i].w *= inv;
        p[tid + i * 256] = v[i];
    }
}

// ---------------------------------------------------------------------------
// pinv init: global max col/row abs sums of attn2 (atomicMax on bits)
// ---------------------------------------------------------------------------
__global__ void init_max_kernel() { g_maxA = 0; g_maxB = 0; }

__global__ __launch_bounds__(256) void colrowmax_kernel() {
    int bh = blockIdx.x, tid = threadIdx.x;
    const float* a = g_attn2 + (size_t)bh * MM * MM;
    float cs = 0.f, rs = 0.f;
    for (int m = 0; m < MM; m++) cs += fabsf(a[(size_t)m * MM + tid]);
    for (int n = 0; n < MM; n++) rs += fabsf(a[(size_t)tid * MM + n]);
    __shared__ float r1[8], r2[8];
    #pragma unroll
    for (int o = 16; o; o >>= 1) {
        cs = fmaxf(cs, __shfl_xor_sync(~0u, cs, o));
        rs = fmaxf(rs, __shfl_xor_sync(~0u, rs, o));
    }
    if ((tid & 31) == 0) { r1[tid >> 5] = cs; r2[tid >> 5] = rs; }
    __syncthreads();
    if (tid == 0) {
        float a1 = r1[0], a2 = r2[0];
        #pragma unroll
        for (int i = 1; i < 8; i++) { a1 = fmaxf(a1, r1[i]); a2 = fmaxf(a2, r2[i]); }
        atomicMax(&g_maxA, __float_as_int(a1));
        atomicMax(&g_maxB, __float_as_int(a2));
    }
}

// z0 = attn2^T * (1/(maxA*maxB)), smem transpose
__global__ __launch_bounds__(256) void z0_kernel() {
    int bh = blockIdx.z;
    int c0 = blockIdx.x * 32, r0 = blockIdx.y * 32;
    int tid = threadIdx.x;
    __shared__ float t[32][33];
    const float* a = g_attn2 + (size_t)bh * MM * MM;
    #pragma unroll
    for (int rr = 0; rr < 4; rr++) {
        int r = rr * 8 + (tid >> 5), c = tid & 31;
        t[r][c] = a[(size_t)(r0 + r) * MM + c0 + c];
    }
    __syncthreads();
    float s = 1.f / (__int_as_float(g_maxA) * __int_as_float(g_maxB));
    float* z = g_z + (size_t)bh * MM * MM;
    #pragma unroll
    for (int rr = 0; rr < 4; rr++) {
        int r = rr * 8 + (tid >> 5), c = tid & 31;
        z[(size_t)(c0 + r) * MM + r0 + c] = t[c][r] * s;
    }
}

// ---------------------------------------------------------------------------
// FFMA batched 256x256: C = alpha*(P@Q) + beta*R (final pinv iteration)
// 128x128 tile, BK=16, 8x8 micro
// ---------------------------------------------------------------------------
__global__ __launch_bounds__(256) void matmul_ba128(const float* __restrict__ P,
                                                    const float* __restrict__ Q,
                                                    const float* __restrict__ R,
                                                    float* __restrict__ C,
                                                    float alpha, float beta) {
    __shared__ float As[16][132];
    __shared__ float Bs[16][132];
    size_t base = (size_t)blockIdx.z * (MM * MM);
    int m0 = blockIdx.y * 128, n0 = blockIdx.x * 128;
    int tid = threadIdx.x;
    int tx = tid & 15, ty = tid >> 4;
    float acc[8][8] = {};
    for (int kk = 0; kk < 256; kk += 16) {
        #pragma unroll
        for (int u = 0; u < 2; u++) {
            int g = u * 256 + tid;
            int m = g >> 2, k4 = g & 3;
            float4 av = *(const float4*)(P + base + (size_t)(m0 + m) * MM + kk + k4 * 4);
            As[k4*4+0][m] = av.x; As[k4*4+1][m] = av.y;
            As[k4*4+2][m] = av.z; As[k4*4+3][m] = av.w;
        }
        #pragma unroll
        for (int u = 0; u < 2; u++) {
            int g = u * 256 + tid;
            int k = g >> 5, n4 = g & 31;
            *(float4*)&Bs[k][n4*4] =
                *(const float4*)(Q + base + (size_t)(kk + k) * MM + n0 + n4 * 4);
        }
        __syncthreads();
        #pragma unroll
        for (int k = 0; k < 16; k++) {
            float a[8], b[8];
            *(float4*)&a[0] = *(const float4*)&As[k][ty*8];
            *(float4*)&a[4] = *(const float4*)&As[k][ty*8+4];
            *(float4*)&b[0] = *(const float4*)&Bs[k][tx*8];
            *(float4*)&b[4] = *(const float4*)&Bs[k][tx*8+4];
            #pragma unroll
            for (int i = 0; i < 8; i++)
                #pragma unroll
                for (int j = 0; j < 8; j++)
                    acc[i][j] += a[i] * b[j];
        }
        __syncthreads();
    }
    #pragma unroll
    for (int i = 0; i < 8; i++) {
        #pragma unroll
        for (int jj = 0; jj < 2; jj++) {
            size_t off = base + (size_t)(m0 + ty * 8 + i) * MM + n0 + tx * 8 + jj * 4;
            float4 rv = make_float4(0.f, 0.f, 0.f, 0.f);
            if (beta != 0.f) rv = *(const float4*)(R + off);
            float4 o;
            o.x = alpha * acc[i][jj*4+0] + beta * rv.x;
            o.y = alpha * acc[i][jj*4+1] + beta * rv.y;
            o.z = alpha * acc[i][jj*4+2] + beta * rv.z;
            o.w = alpha * acc[i][jj*4+3] + beta * rv.w;
            *(float4*)(C + off) = o;
        }
    }
}

// ---------------------------------------------------------------------------
// reduce k-split partials of attn3@v
// ---------------------------------------------------------------------------
__global__ __launch_bounds__(256) void reduce_p3() {
    size_t t = (size_t)blockIdx.x * 256 + threadIdx.x;   // 32*256*64 = 524288
    size_t bh = t >> 14, rem = t & 16383;
    float s = 0.f;
    #pragma unroll
    for (int ks = 0; ks < KS; ks++)
        s += g_p3[((bh * KS + ks) << 14) + rem];
    g_out3[t] = s;
}

// ---------------------------------------------------------------------------
// Depthwise conv-33 residual of v -> y[b,n,h*64+d]
// ---------------------------------------------------------------------------
__global__ __launch_bounds__(256) void conv_kernel(const float* __restrict__ res_w) {
    __shared__ float sv[160][64];
    __shared__ float sw[33];
    int bh = blockIdx.y, n0 = blockIdx.x * 128;
    int b = bh >> 3, h = bh & 7;
    int tid = threadIdx.x;
    if (tid < 33) sw[tid] = res_w[h * 33 + tid];
    const float* vb = g_v + (size_t)bh * NN * DH;
    #pragma unroll
    for (int i = 0; i < 10; i++) {
        int idx = tid + i * 256;
        int r = idx >> 4, c4 = idx & 15;
        int tok = n0 - 16 + r;
        float4 val = make_float4(0.f, 0.f, 0.f, 0.f);
        if (tok >= 0 && tok < NN)
            val = *(const float4*)(vb + (size_t)tok * DH + c4 * 4);
        *(float4*)&sv[r][c4 * 4] = val;
    }
    __syncthreads();
    #pragma unroll
    for (int i = 0; i < 8; i++) {
        int idx = tid + i * 256;
        int nl = idx >> 4, dg = idx & 15;
        float4 acc = make_float4(0.f, 0.f, 0.f, 0.f);
        #pragma unroll
        for (int j = 0; j < 33; j++) {
            float w = sw[j];
            float4 vv = *(const float4*)&sv[nl + j][dg * 4];
            acc.x += w * vv.x; acc.y += w * vv.y;
            acc.z += w * vv.z; acc.w += w * vv.w;
        }
        *(float4*)(g_y + ((size_t)b * NN + n0 + nl) * DD + h * 64 + dg * 4) = acc;
    }
}

// ---------------------------------------------------------------------------
// Launch
// ---------------------------------------------------------------------------
extern "C" void kernel_launch(void* const* d_in, const int* in_sizes, int n_in,
                              void* d_out, int out_size) {
    const float* x     = (const float*)d_in[0];
    const float* ln_w  = (const float*)d_in[1];
    const float* ln_b  = (const float*)d_in[2];
    const float* w_qkv = (const float*)d_in[3];
    const float* w_out = (const float*)d_in[4];
    const float* b_out = (const float*)d_in[5];
    const float* res_w = (const float*)d_in[6];
    float* out = (float*)d_out;

    float *p_xn, *p_q, *p_k, *p_v, *p_ql, *p_kl, *p_attn2;
    float *p_z, *p_z2, *p_xz, *p_t, *p_u;
    float *p_sim3, *p_sim1, *p_p3, *p_out3, *p_wc, *p_y;
    cudaGetSymbolAddress((void**)&p_xn, g_xn);
    cudaGetSymbolAddress((void**)&p_q,  g_q);
    cudaGetSymbolAddress((void**)&p_k,  g_k);
    cudaGetSymbolAddress((void**)&p_v,  g_v);
    cudaGetSymbolAddress((void**)&p_ql, g_ql);
    cudaGetSymbolAddress((void**)&p_kl, g_kl);
    cudaGetSymbolAddress((void**)&p_attn2, g_attn2);
    cudaGetSymbolAddress((void**)&p_z,  g_z);
    cudaGetSymbolAddress((void**)&p_z2, g_z2);
    cudaGetSymbolAddress((void**)&p_xz, g_xz);
    cudaGetSymbolAddress((void**)&p_t,  g_t);
    cudaGetSymbolAddress((void**)&p_u,  g_u);
    cudaGetSymbolAddress((void**)&p_sim3, g_sim3);
    cudaGetSymbolAddress((void**)&p_sim1, g_sim1);
    cudaGetSymbolAddress((void**)&p_p3, g_p3);
    cudaGetSymbolAddress((void**)&p_out3, g_out3);
    cudaGetSymbolAddress((void**)&p_wc, g_wc);
    cudaGetSymbolAddress((void**)&p_y,  g_y);

    // LN -> QKV (tf32) -> landmarks
    ln_kernel<<<BB * NN, 128>>>(x, ln_w, ln_b);
    tc_gemm<0,128,128,32,false><<<dim3(12, 256, 1), 256>>>(
        p_xn, w_qkv, nullptr, nullptr, nullptr,
        1536, 512, 512, 1536, 0, 0, 0, 0.f, 0.f);
    landmark_kernel<<<dim3(MM, BH), 64>>>();

    // sim2 (fp32), sim3 + sim1 (tf32 NT)
    gemm_sim2<<<dim3(2, 2, BH), 256>>>();
    tc_gemm<2,128,128,32,true><<<dim3(64, 2, BH), 256>>>(
        p_ql, p_k, p_sim3, nullptr, nullptr,
        NN, 64, 64, 64, (long long)MM*DH, (long long)NN*DH, (long long)MM*NN, 0.f, 0.f);
    tc_gemm<2,128,128,32,true><<<dim3(2, 64, BH), 256>>>(
        p_q, p_kl, p_sim1, nullptr, nullptr,
        MM, 64, 64, 64, (long long)NN*DH, (long long)MM*DH, (long long)NN*MM, 0.f, 0.f);

    // softmaxes
    softmax256<<<BH * MM, 256>>>();                 // attn2
    softmax8192<<<BH * MM, 256>>>();                // attn3 (g_sim3)
    softmax256w<<<BH * NN / 8, 256>>>(p_sim1);      // attn1 (g_sim1)

    // pinv
    init_max_kernel<<<1, 1>>>();
    colrowmax_kernel<<<BH, 256>>>();
    z0_kernel<<<dim3(8, 8, BH), 256>>>();

    dim3 gba(2, 2, BH);
    float *zc = p_z, *zn = p_z2;
    for (int it = 0; it < 5; it++) {   // iterations 0..4 in tf32
        tc_gemm<4,128,128,32,false><<<gba, 256>>>(p_attn2, zc, p_xz, nullptr, nullptr,
            MM, 256, 256, 256, (long long)MM*MM, (long long)MM*MM, (long long)MM*MM, 1.f, 0.f);
        tc_gemm<4,128,128,32,false><<<gba, 256>>>(p_xz, p_xz, p_t, p_xz, nullptr,
            MM, 256, 256, 256, (long long)MM*MM, (long long)MM*MM, (long long)MM*MM, -1.f, 7.f);
        tc_gemm<4,128,128,32,false><<<gba, 256>>>(p_xz, p_t, p_u, p_xz, nullptr,
            MM, 256, 256, 256, (long long)MM*MM, (long long)MM*MM, (long long)MM*MM, -1.f, 15.f);
        tc_gemm<4,128,128,32,false><<<gba, 256>>>(zc, p_u, zn, zc, nullptr,
            MM, 256, 256, 256, (long long)MM*MM, (long long)MM*MM, (long long)MM*MM, -0.25f, 3.25f);
        float* tmp = zc; zc = zn; zn = tmp;
    }
    // final iteration in fp32 FFMA
    matmul_ba128<<<gba, 256>>>(p_attn2, zc, nullptr, p_xz, 1.f, 0.f);
    matmul_ba128<<<gba, 256>>>(p_xz, p_xz, p_xz, p_t, -1.f, 7.f);
    matmul_ba128<<<gba, 256>>>(p_xz, p_t, p_xz, p_u, -1.f, 15.f);
    matmul_ba128<<<gba, 256>>>(zc, p_u, zc, zn, -0.25f, 3.25f);
    { float* tmp = zc; zc = zn; zn = tmp; }

    // out3 = attn3 @ v (tf32, k-split 16) then reduce
    tc_gemm<3,128,64,32,false><<<dim3(1, 2, BH * KS), 256>>>(
        p_sim3, p_v, p_p3, nullptr, nullptr,
        64, 512, NN, 64, 0, 0, 0, 0.f, 0.f);
    reduce_p3<<<2048, 256>>>();

    // Wc = z_final @ out3 (tf32)
    tc_gemm<2,128,64,32,false><<<dim3(1, 2, BH), 256>>>(
        zc, p_out3, p_wc, nullptr, nullptr,
        64, 256, 256, 64, (long long)MM*MM, (long long)MM*DH, (long long)MM*DH, 0.f, 0.f);

    // y = conv residual ; y += attn1 @ Wc (tf32)
    conv_kernel<<<dim3(64, BH), 256>>>(res_w);
    tc_gemm<5,128,64,32,false><<<dim3(1, 64, BH), 256>>>(
        p_sim1, p_wc, p_y, nullptr, nullptr,
        64, 256, 256, 64, (long long)NN*MM, (long long)MM*DH, 0, 0.f, 0.f);

    // out = y @ w_out + b_out + x (tf32)
    tc_gemm<1,128,128,32,false><<<dim3(4, 256, 1), 256>>>(
        p_y, w_out, out, b_out, x,
        512, 512, 512, 512, 0, 0, 0, 0.f, 0.f);
}

// round 6
// speedup vs baseline: 2.2399x; 1.3923x over previous
#include <cuda_runtime.h>
#include <cuda_bf16.h>
#include <stdint.h>
#include <math.h>

// ---------------------------------------------------------------------------
// Constants: B=4, N=8192, DIM=512, HEADS=8, DH=64, M=256 landmarks, l=32
// ---------------------------------------------------------------------------
#define BB 4
#define NN 8192
#define DD 512
#define HH 8
#define DH 64
#define MM 256
#define BH 32
#define KS 16   /* k-split for attn3@v */

// ---------------------------------------------------------------------------
// Scratch (device globals; allocation is forbidden)
// ---------------------------------------------------------------------------
__device__ __align__(16) float g_xn  [(size_t)BB*NN*DD];
__device__ __align__(16) float g_q   [(size_t)BH*NN*DH];
__device__ __align__(16) float g_k   [(size_t)BH*NN*DH];
__device__ __align__(16) float g_v   [(size_t)BH*NN*DH];
__device__ __align__(16) float g_ql  [(size_t)BH*MM*DH];
__device__ __align__(16) float g_kl  [(size_t)BH*MM*DH];
__device__ __align__(16) float g_attn2[(size_t)BH*MM*MM];
__device__ __align__(16) float g_z   [(size_t)BH*MM*MM];
__device__ __align__(16) float g_z2  [(size_t)BH*MM*MM];
__device__ __align__(16) float g_xz  [(size_t)BH*MM*MM];
__device__ __align__(16) float g_t   [(size_t)BH*MM*MM];
__device__ __align__(16) float g_u   [(size_t)BH*MM*MM];
__device__ __align__(16) __nv_bfloat16 g_h3[(size_t)BH*MM*NN];  // attn3 scores/probs bf16
__device__ __align__(16) __nv_bfloat16 g_h1[(size_t)BH*NN*MM];  // attn1 probs bf16
__device__ __align__(16) float g_p3  [(size_t)BH*KS*MM*DH];
__device__ __align__(16) float g_out3[(size_t)BH*MM*DH];
__device__ __align__(16) float g_wc  [(size_t)BH*MM*DH];
__device__ __align__(16) float g_y   [(size_t)BB*NN*DD];
__device__ int g_maxA;
__device__ int g_maxB;

// ---------------------------------------------------------------------------
// Conversion helpers
// ---------------------------------------------------------------------------
__device__ __forceinline__ uint32_t f2tf(float f) {
    uint32_t u;
    asm("cvt.rna.tf32.f32 %0, %1;" : "=r"(u) : "f"(f));
    return u;
}
// pack (lo,hi) floats -> bf16x2 with lo in low 16 bits
__device__ __forceinline__ uint32_t f2bf2(float lo, float hi) {
    uint32_t r;
    asm("cvt.rn.bf16x2.f32 %0, %1, %2;" : "=r"(r) : "f"(hi), "f"(lo));
    return r;
}

__device__ __forceinline__ void mma8(float* d, const uint32_t* a, const uint32_t* b) {
    asm volatile(
        "mma.sync.aligned.m16n8k8.row.col.f32.tf32.tf32.f32 "
        "{%0,%1,%2,%3}, {%4,%5,%6,%7}, {%8,%9}, {%0,%1,%2,%3};"
        : "+f"(d[0]), "+f"(d[1]), "+f"(d[2]), "+f"(d[3])
        : "r"(a[0]), "r"(a[1]), "r"(a[2]), "r"(a[3]), "r"(b[0]), "r"(b[1]));
}
__device__ __forceinline__ void mma16(float* d, const uint32_t* a, const uint32_t* b) {
    asm volatile(
        "mma.sync.aligned.m16n8k16.row.col.f32.bf16.bf16.f32 "
        "{%0,%1,%2,%3}, {%4,%5,%6,%7}, {%8,%9}, {%0,%1,%2,%3};"
        : "+f"(d[0]), "+f"(d[1]), "+f"(d[2]), "+f"(d[3])
        : "r"(a[0]), "r"(a[1]), "r"(a[2]), "r"(a[3]), "r"(b[0]), "r"(b[1]));
}

// ---------------------------------------------------------------------------
// TF32 tensor-core GEMM (pinv + Wc): 256 thr, 8 warps (2m x 4n)
// EPI: 2=plain batched store  4=alpha*(PQ)+beta*R batched
// ---------------------------------------------------------------------------
template<int EPI, int BM, int BN, int BK, bool TRB>
__global__ __launch_bounds__(256) void tc_gemm(
    const float* __restrict__ A, const float* __restrict__ Bg,
    float* __restrict__ C, const float* __restrict__ X1,
    int N, int K, int lda, int ldb,
    long long bsA, long long bsB, long long bsC,
    float alpha, float beta)
{
    constexpr int PA = BM + 8, PB = BN + 8;
    constexpr int MT = (BM / 2) / 16;
    constexpr int NT = (BN / 4) / 8;
    __shared__ uint32_t As[BK][PA];
    __shared__ uint32_t Bs[BK][PB];

    int tid = threadIdx.x, lane = tid & 31, warp = tid >> 5;
    int wm0 = (warp >> 2) * (BM / 2);
    int wn0 = (warp & 3) * (BN / 4);
    int z = blockIdx.z;
    int m0 = blockIdx.y * BM, n0 = blockIdx.x * BN;

    const float* Ab = A  + (size_t)z * bsA;
    const float* Bb = Bg + (size_t)z * bsB;

    float acc[MT][NT][4];
    #pragma unroll
    for (int i = 0; i < MT; i++)
        #pragma unroll
        for (int j = 0; j < NT; j++)
            #pragma unroll
            for (int r = 0; r < 4; r++) acc[i][j][r] = 0.f;

    for (int k0 = 0; k0 < K; k0 += BK) {
        #pragma unroll
        for (int c = 0; c < (BM * BK) / 1024; c++) {
            int id = c * 256 + tid;
            int m  = id / (BK / 4);
            int kq = id % (BK / 4);
            float4 v = *(const float4*)(Ab + (size_t)(m0 + m) * lda + k0 + kq * 4);
            As[kq*4+0][m] = f2tf(v.x); As[kq*4+1][m] = f2tf(v.y);
            As[kq*4+2][m] = f2tf(v.z); As[kq*4+3][m] = f2tf(v.w);
        }
        if constexpr (!TRB) {
            #pragma unroll
            for (int c = 0; c < (BK * BN) / 1024; c++) {
                int id = c * 256 + tid;
                int k  = id / (BN / 4);
                int nq = id % (BN / 4);
                float4 v = *(const float4*)(Bb + (size_t)(k0 + k) * ldb + n0 + nq * 4);
                Bs[k][nq*4+0] = f2tf(v.x); Bs[k][nq*4+1] = f2tf(v.y);
                Bs[k][nq*4+2] = f2tf(v.z); Bs[k][nq*4+3] = f2tf(v.w);
            }
        } else {
            #pragma unroll
            for (int c = 0; c < (BN * BK) / 1024; c++) {
                int id = c * 256 + tid;
                int n  = id / (BK / 4);
                int kq = id % (BK / 4);
                float4 v = *(const float4*)(Bb + (size_t)(n0 + n) * ldb + k0 + kq * 4);
                Bs[kq*4+0][n] = f2tf(v.x); Bs[kq*4+1][n] = f2tf(v.y);
                Bs[kq*4+2][n] = f2tf(v.z); Bs[kq*4+3][n] = f2tf(v.w);
            }
        }
        __syncthreads();
        #pragma unroll
        for (int ks = 0; ks < BK / 8; ks++) {
            uint32_t af[MT][4], bf[NT][2];
            int kr = ks * 8 + (lane & 3);
            int mr = wm0 + (lane >> 2);
            #pragma unroll
            for (int mt = 0; mt < MT; mt++) {
                af[mt][0] = As[kr    ][mr + mt * 16];
                af[mt][1] = As[kr    ][mr + mt * 16 + 8];
                af[mt][2] = As[kr + 4][mr + mt * 16];
                af[mt][3] = As[kr + 4][mr + mt * 16 + 8];
            }
            int nr = wn0 + (lane >> 2);
            #pragma unroll
            for (int nt = 0; nt < NT; nt++) {
                bf[nt][0] = Bs[kr    ][nr + nt * 8];
                bf[nt][1] = Bs[kr + 4][nr + nt * 8];
            }
            #pragma unroll
            for (int mt = 0; mt < MT; mt++)
                #pragma unroll
                for (int nt = 0; nt < NT; nt++)
                    mma8(acc[mt][nt], af[mt], bf[nt]);
        }
        __syncthreads();
    }

    #pragma unroll
    for (int mt = 0; mt < MT; mt++) {
        #pragma unroll
        for (int nt = 0; nt < NT; nt++) {
            int row = m0 + wm0 + mt * 16 + (lane >> 2);
            int col = n0 + wn0 + nt * 8 + (lane & 3) * 2;
            float2 lo = make_float2(acc[mt][nt][0], acc[mt][nt][1]);
            float2 hi = make_float2(acc[mt][nt][2], acc[mt][nt][3]);
            if constexpr (EPI == 2) {
                size_t base = (size_t)z * bsC;
                *(float2*)(C + base + (size_t)row       * N + col) = lo;
                *(float2*)(C + base + (size_t)(row + 8) * N + col) = hi;
            } else if constexpr (EPI == 4) {
                size_t base = (size_t)z * (MM * MM);
                size_t r1 = base + (size_t)row * MM + col;
                size_t r2 = base + (size_t)(row + 8) * MM + col;
                float2 rv1 = make_float2(0.f, 0.f), rv2 = make_float2(0.f, 0.f);
                if (beta != 0.f) {
                    rv1 = *(const float2*)(X1 + r1);
                    rv2 = *(const float2*)(X1 + r2);
                }
                *(float2*)(C + r1) = make_float2(alpha*lo.x + beta*rv1.x, alpha*lo.y + beta*rv1.y);
                *(float2*)(C + r2) = make_float2(alpha*hi.x + beta*rv2.x, alpha*hi.y + beta*rv2.y);
            }
        }
    }
}

// ---------------------------------------------------------------------------
// BF16 tensor-core GEMM (m16n8k16), 256 thr, 8 warps (2m x 4n)
// EPI: 0=QKV scatter  1=out+bias+x  3=p3 partial (k-split via z)
//      5=y += scatter  6=bf16 plain batched store
// BFA: A operand already bf16 in gmem; TRB: B is [N,K] f32 row-major
// ---------------------------------------------------------------------------
template<int EPI, int BM, int BN, int BK, bool TRB, bool BFA>
__global__ __launch_bounds__(256) void bf_gemm(
    const void* __restrict__ Av, const float* __restrict__ Bg,
    void* __restrict__ Cv, const float* __restrict__ X1, const float* __restrict__ X2,
    int N, int K, int lda, int ldb,
    long long bsA, long long bsB, long long bsC)
{
    constexpr int PA = BM + 8, PB = BN + 8;
    constexpr int MT = (BM / 2) / 16;
    constexpr int NT = (BN / 4) / 8;
    __shared__ uint32_t As[BK/2][PA];
    __shared__ uint32_t Bs[BK/2][PB];

    int tid = threadIdx.x, lane = tid & 31, warp = tid >> 5;
    int wm0 = (warp >> 2) * (BM / 2);
    int wn0 = (warp & 3) * (BN / 4);
    int z = blockIdx.z;
    int m0 = blockIdx.y * BM, n0 = blockIdx.x * BN;

    const float* Bb;
    const float* Abf = nullptr;
    const __nv_bfloat16* Abh = nullptr;
    if constexpr (EPI == 3) {
        int bh = z >> 4, ks = z & 15;
        Abh = (const __nv_bfloat16*)Av + (size_t)bh * MM * NN + (size_t)ks * 512;
        Bb  = Bg + (size_t)bh * NN * DH + (size_t)ks * 512 * DH;
    } else {
        if constexpr (BFA) Abh = (const __nv_bfloat16*)Av + (size_t)z * bsA;
        else               Abf = (const float*)Av + (size_t)z * bsA;
        Bb = Bg + (size_t)z * bsB;
    }
    if constexpr (EPI == 3 && !BFA) { /* unreachable */ }

    float acc[MT][NT][4];
    #pragma unroll
    for (int i = 0; i < MT; i++)
        #pragma unroll
        for (int j = 0; j < NT; j++)
            #pragma unroll
            for (int r = 0; r < 4; r++) acc[i][j][r] = 0.f;

    for (int k0 = 0; k0 < K; k0 += BK) {
        // ---- A tile
        if constexpr (BFA || EPI == 3) {
            #pragma unroll
            for (int c = 0; c < (BM * BK) / 2048; c++) {
                int id = c * 256 + tid;
                int m  = id / (BK / 8);
                int kq = id % (BK / 8);
                uint4 v = *(const uint4*)(Abh + (size_t)(m0 + m) * lda + k0 + kq * 8);
                As[kq*4+0][m] = v.x; As[kq*4+1][m] = v.y;
                As[kq*4+2][m] = v.z; As[kq*4+3][m] = v.w;
            }
        } else {
            #pragma unroll
            for (int c = 0; c < (BM * BK) / 1024; c++) {
                int id = c * 256 + tid;
                int m  = id / (BK / 4);
                int kq = id % (BK / 4);
                float4 v = *(const float4*)(Abf + (size_t)(m0 + m) * lda + k0 + kq * 4);
                As[kq*2+0][m] = f2bf2(v.x, v.y);
                As[kq*2+1][m] = f2bf2(v.z, v.w);
            }
        }
        // ---- B tile (f32 source)
        if constexpr (!TRB) {
            #pragma unroll
            for (int c = 0; c < (BK / 2) * (BN / 4) / 256; c++) {
                int id = c * 256 + tid;
                int kp = id / (BN / 4);
                int nq = id % (BN / 4);
                float4 lo = *(const float4*)(Bb + (size_t)(k0 + 2*kp    ) * ldb + n0 + nq * 4);
                float4 hi = *(const float4*)(Bb + (size_t)(k0 + 2*kp + 1) * ldb + n0 + nq * 4);
                Bs[kp][nq*4+0] = f2bf2(lo.x, hi.x);
                Bs[kp][nq*4+1] = f2bf2(lo.y, hi.y);
                Bs[kp][nq*4+2] = f2bf2(lo.z, hi.z);
                Bs[kp][nq*4+3] = f2bf2(lo.w, hi.w);
            }
        } else {
            #pragma unroll
            for (int c = 0; c < (BN * BK) / 1024; c++) {
                int id = c * 256 + tid;
                int n  = id / (BK / 4);
                int kq = id % (BK / 4);
                float4 v = *(const float4*)(Bb + (size_t)(n0 + n) * ldb + k0 + kq * 4);
                Bs[kq*2+0][n] = f2bf2(v.x, v.y);
                Bs[kq*2+1][n] = f2bf2(v.z, v.w);
            }
        }
        __syncthreads();
        #pragma unroll
        for (int ks = 0; ks < BK / 16; ks++) {
            uint32_t af[MT][4], bf[NT][2];
            int kr = ks * 8 + (lane & 3);
            int mr = wm0 + (lane >> 2);
            #pragma unroll
            for (int mt = 0; mt < MT; mt++) {
                af[mt][0] = As[kr    ][mr + mt * 16];
                af[mt][1] = As[kr    ][mr + mt * 16 + 8];
                af[mt][2] = As[kr + 4][mr + mt * 16];
                af[mt][3] = As[kr + 4][mr + mt * 16 + 8];
            }
            int nr = wn0 + (lane >> 2);
            #pragma unroll
            for (int nt = 0; nt < NT; nt++) {
                bf[nt][0] = Bs[kr    ][nr + nt * 8];
                bf[nt][1] = Bs[kr + 4][nr + nt * 8];
            }
            #pragma unroll
            for (int mt = 0; mt < MT; mt++)
                #pragma unroll
                for (int nt = 0; nt < NT; nt++)
                    mma16(acc[mt][nt], af[mt], bf[nt]);
        }
        __syncthreads();
    }

    #pragma unroll
    for (int mt = 0; mt < MT; mt++) {
        #pragma unroll
        for (int nt = 0; nt < NT; nt++) {
            int row = m0 + wm0 + mt * 16 + (lane >> 2);
            int col = n0 + wn0 + nt * 8 + (lane & 3) * 2;
            float2 lo = make_float2(acc[mt][nt][0], acc[mt][nt][1]);
            float2 hi = make_float2(acc[mt][nt][2], acc[mt][nt][3]);
            if constexpr (EPI == 0) {
                int which = col >> 9, inner = col & 511;
                int h = inner >> 6, d = inner & 63;
                float* dst = which == 0 ? g_q : (which == 1 ? g_k : g_v);
                float s = (which == 0) ? 0.125f : 1.f;
                int bq = row >> 13, n = row & (NN - 1);
                *(float2*)(dst + (((size_t)(bq*HH+h))*NN + n    )*DH + d) = make_float2(lo.x*s, lo.y*s);
                *(float2*)(dst + (((size_t)(bq*HH+h))*NN + n + 8)*DH + d) = make_float2(hi.x*s, hi.y*s);
            } else if constexpr (EPI == 1) {
                float* C = (float*)Cv;
                float2 bv = *(const float2*)(X1 + col);
                size_t r1 = (size_t)row * DD + col, r2 = (size_t)(row + 8) * DD + col;
                float2 x1 = *(const float2*)(X2 + r1);
                float2 x2 = *(const float2*)(X2 + r2);
                *(float2*)(C + r1) = make_float2(lo.x + bv.x + x1.x, lo.y + bv.y + x1.y);
                *(float2*)(C + r2) = make_float2(hi.x + bv.x + x2.x, hi.y + bv.y + x2.y);
            } else if constexpr (EPI == 3) {
                float* C = (float*)Cv;
                size_t base = (size_t)z * (MM * DH);
                *(float2*)(C + base + (row    ) * DH + col) = lo;
                *(float2*)(C + base + (row + 8) * DH + col) = hi;
            } else if constexpr (EPI == 5) {
                float* C = (float*)Cv;
                int b = z >> 3, h = z & 7;
                size_t r1 = ((size_t)b * NN + row    ) * DD + h * 64 + col;
                size_t r2 = ((size_t)b * NN + row + 8) * DD + h * 64 + col;
                float2 y1 = *(float2*)(C + r1);
                float2 y2 = *(float2*)(C + r2);
                *(float2*)(C + r1) = make_float2(y1.x + lo.x, y1.y + lo.y);
                *(float2*)(C + r2) = make_float2(y2.x + hi.x, y2.y + hi.y);
            } else if constexpr (EPI == 6) {
                __nv_bfloat16* C = (__nv_bfloat16*)Cv;
                size_t base = (size_t)z * bsC;
                *(uint32_t*)(C + base + (size_t)row       * N + col) = f2bf2(lo.x, lo.y);
                *(uint32_t*)(C + base + (size_t)(row + 8) * N + col) = f2bf2(hi.x, hi.y);
            }
        }
    }
}

// ---------------------------------------------------------------------------
// Fused sim1 + softmax: attn1 = softmax(q @ kl^T) rows of 256, bf16 out
// BM=64 rows/block, BN=256 (full row), K=64, 8 warps (2m x 4n)
// ---------------------------------------------------------------------------
__global__ __launch_bounds__(256) void sim1_fused() {
    __shared__ uint32_t As[16][72];    // K/2=16... per BK=32 chunk: 16 rows
    __shared__ uint32_t Bs[16][264];
    __shared__ float rmax[64][5];
    __shared__ float rsum[64][5];

    int tid = threadIdx.x, lane = tid & 31, warp = tid >> 5;
    int wm0 = (warp >> 2) * 32;        // 2 m-warps * 32 rows
    int wn0 = (warp & 3) * 64;         // 4 n-warps * 64 cols
    int bh = blockIdx.z;
    int m0 = blockIdx.y * 64;
    const float* Ab = g_q  + ((size_t)bh * NN + m0) * DH;
    const float* Bb = g_kl + (size_t)bh * MM * DH;

    float acc[2][8][4];
    #pragma unroll
    for (int i = 0; i < 2; i++)
        #pragma unroll
        for (int j = 0; j < 8; j++)
            #pragma unroll
            for (int r = 0; r < 4; r++) acc[i][j][r] = 0.f;

    for (int k0 = 0; k0 < 64; k0 += 32) {
        // A: 64 rows x 32 k -> 2048 f32 = 512 float4; 2 per thread
        #pragma unroll
        for (int c = 0; c < 2; c++) {
            int id = c * 256 + tid;
            int m = id >> 3, kq = id & 7;
            float4 v = *(const float4*)(Ab + (size_t)m * DH + k0 + kq * 4);
            As[kq*2+0][m] = f2bf2(v.x, v.y);
            As[kq*2+1][m] = f2bf2(v.z, v.w);
        }
        // B (TRB): 256 rows x 32 k -> 8 per thread
        #pragma unroll
        for (int c = 0; c < 8; c++) {
            int id = c * 256 + tid;
            int n = id >> 3, kq = id & 7;
            float4 v = *(const float4*)(Bb + (size_t)n * DH + k0 + kq * 4);
            Bs[kq*2+0][n] = f2bf2(v.x, v.y);
            Bs[kq*2+1][n] = f2bf2(v.z, v.w);
        }
        __syncthreads();
        #pragma unroll
        for (int ks = 0; ks < 2; ks++) {
            uint32_t af[2][4], bf[8][2];
            int kr = ks * 8 + (lane & 3);
            int mr = wm0 + (lane >> 2);
            #pragma unroll
            for (int mt = 0; mt < 2; mt++) {
                af[mt][0] = As[kr    ][mr + mt * 16];
                af[mt][1] = As[kr    ][mr + mt * 16 + 8];
                af[mt][2] = As[kr + 4][mr + mt * 16];
                af[mt][3] = As[kr + 4][mr + mt * 16 + 8];
            }
            int nr = wn0 + (lane >> 2);
            #pragma unroll
            for (int nt = 0; nt < 8; nt++) {
                bf[nt][0] = Bs[kr    ][nr + nt * 8];
                bf[nt][1] = Bs[kr + 4][nr + nt * 8];
            }
            #pragma unroll
            for (int mt = 0; mt < 2; mt++)
                #pragma unroll
                for (int nt = 0; nt < 8; nt++)
                    mma16(acc[mt][nt], af[mt], bf[nt]);
        }
        __syncthreads();
    }

    // ---- softmax over full 256-wide rows -----------------------------------
    int g = lane >> 2, q4 = lane & 3;
    int wn = warp & 3;
    // partial row max: each thread covers 16 cols of each of its 4 rows
    #pragma unroll
    for (int mt = 0; mt < 2; mt++) {
        int r0 = wm0 + mt * 16 + g;      // local row (lo half)
        float m0v = -1e30f, m1v = -1e30f;
        #pragma unroll
        for (int nt = 0; nt < 8; nt++) {
            m0v = fmaxf(m0v, fmaxf(acc[mt][nt][0], acc[mt][nt][1]));
            m1v = fmaxf(m1v, fmaxf(acc[mt][nt][2], acc[mt][nt][3]));
        }
        // reduce over quad (lane&3)
        #pragma unroll
        for (int o = 1; o < 4; o <<= 1) {
            m0v = fmaxf(m0v, __shfl_xor_sync(~0u, m0v, o));
            m1v = fmaxf(m1v, __shfl_xor_sync(~0u, m1v, o));
        }
        if (q4 == 0) { rmax[r0][wn] = m0v; rmax[r0 + 8][wn] = m1v; }
    }
    __syncthreads();
    // exp + partial sums
    #pragma unroll
    for (int mt = 0; mt < 2; mt++) {
        int r0 = wm0 + mt * 16 + g;
        float M0 = fmaxf(fmaxf(rmax[r0][0], rmax[r0][1]), fmaxf(rmax[r0][2], rmax[r0][3]));
        float M1 = fmaxf(fmaxf(rmax[r0+8][0], rmax[r0+8][1]), fmaxf(rmax[r0+8][2], rmax[r0+8][3]));
        float s0 = 0.f, s1 = 0.f;
        #pragma unroll
        for (int nt = 0; nt < 8; nt++) {
            acc[mt][nt][0] = __expf(acc[mt][nt][0] - M0);
            acc[mt][nt][1] = __expf(acc[mt][nt][1] - M0);
            acc[mt][nt][2] = __expf(acc[mt][nt][2] - M1);
            acc[mt][nt][3] = __expf(acc[mt][nt][3] - M1);
            s0 += acc[mt][nt][0] + acc[mt][nt][1];
            s1 += acc[mt][nt][2] + acc[mt][nt][3];
        }
        #pragma unroll
        for (int o = 1; o < 4; o <<= 1) {
            s0 += __shfl_xor_sync(~0u, s0, o);
            s1 += __shfl_xor_sync(~0u, s1, o);
        }
        if (q4 == 0) { rsum[r0][wn] = s0; rsum[r0 + 8][wn] = s1; }
    }
    __syncthreads();
    // normalize + bf16 store
    __nv_bfloat16* O = g_h1 + ((size_t)bh * NN + m0) * MM;
    #pragma unroll
    for (int mt = 0; mt < 2; mt++) {
        int r0 = wm0 + mt * 16 + g;
        float i0 = 1.f / (rsum[r0][0] + rsum[r0][1] + rsum[r0][2] + rsum[r0][3]);
        float i1 = 1.f / (rsum[r0+8][0] + rsum[r0+8][1] + rsum[r0+8][2] + rsum[r0+8][3]);
        #pragma unroll
        for (int nt = 0; nt < 8; nt++) {
            int col = wn0 + nt * 8 + q4 * 2;
            *(uint32_t*)(O + (size_t)r0 * MM + col) =
                f2bf2(acc[mt][nt][0] * i0, acc[mt][nt][1] * i0);
            *(uint32_t*)(O + (size_t)(r0 + 8) * MM + col) =
                f2bf2(acc[mt][nt][2] * i1, acc[mt][nt][3] * i1);
        }
    }
}

// ---------------------------------------------------------------------------
// LayerNorm
// ---------------------------------------------------------------------------
__global__ __launch_bounds__(128) void ln_kernel(const float* __restrict__ x,
                                                 const float* __restrict__ w,
                                                 const float* __restrict__ bia) {
    int row = blockIdx.x, tid = threadIdx.x;
    const float4* xr = reinterpret_cast<const float4*>(x + (size_t)row * DD);
    float4 v = xr[tid];
    float s  = v.x + v.y + v.z + v.w;
    float sq = v.x*v.x + v.y*v.y + v.z*v.z + v.w*v.w;
    __shared__ float sm[4], sm2[4];
    #pragma unroll
    for (int o = 16; o > 0; o >>= 1) {
        s  += __shfl_down_sync(0xffffffffu, s,  o);
        sq += __shfl_down_sync(0xffffffffu, sq, o);
    }
    if ((tid & 31) == 0) { sm[tid >> 5] = s; sm2[tid >> 5] = sq; }
    __syncthreads();
    if (tid == 0) {
        float a = 0.f, b2 = 0.f;
        #pragma unroll
        for (int i = 0; i < 4; i++) { a += sm[i]; b2 += sm2[i]; }
        sm[0] = a; sm2[0] = b2;
    }
    __syncthreads();
    float mean = sm[0] * (1.f / 512.f);
    float var  = sm2[0] * (1.f / 512.f) - mean * mean;
    float rstd = rsqrtf(var + 1e-5f);
    float4 wv = reinterpret_cast<const float4*>(w)[tid];
    float4 bv = reinterpret_cast<const float4*>(bia)[tid];
    float4 o;
    o.x = (v.x - mean) * rstd * wv.x + bv.x;
    o.y = (v.y - mean) * rstd * wv.y + bv.y;
    o.z = (v.z - mean) * rstd * wv.z + bv.z;
    o.w = (v.w - mean) * rstd * wv.w + bv.w;
    reinterpret_cast<float4*>(g_xn + (size_t)row * DD)[tid] = o;
}

// ---------------------------------------------------------------------------
// Landmarks
// ---------------------------------------------------------------------------
__global__ void landmark_kernel() {
    int m = blockIdx.x, bh = blockIdx.y;
    int d = threadIdx.x;
    size_t base = ((size_t)bh * NN + (size_t)m * 32) * DH + d;
    float sq = 0.f, sk = 0.f;
    #pragma unroll
    for (int j = 0; j < 32; j++) {
        sq += g_q[base + (size_t)j * DH];
        sk += g_k[base + (size_t)j * DH];
    }
    size_t o = ((size_t)bh * MM + m) * DH + d;
    g_ql[o] = sq * (1.f / 32.f);
    g_kl[o] = sk * (1.f / 32.f);
}

// ---------------------------------------------------------------------------
// sim2 (FFMA fp32, feeds pinv)
// ---------------------------------------------------------------------------
__global__ __launch_bounds__(256) void gemm_sim2() {
    __shared__ float As[32][132];
    __shared__ float Bs[32][132];
    int bh = blockIdx.z;
    int n0 = blockIdx.x * 128, m0 = blockIdx.y * 128;
    const float* Ab = g_ql + ((size_t)bh * MM + m0) * DH;
    const float* Bb = g_kl + ((size_t)bh * MM + n0) * DH;
    float* Cb = g_attn2 + (size_t)bh * MM * MM;
    int tid = threadIdx.x;
    int tx = tid & 15, ty = tid >> 4;
    float acc[8][8] = {};
    for (int kk = 0; kk < 64; kk += 32) {
        #pragma unroll
        for (int u = 0; u < 4; u++) {
            int g = u * 256 + tid;
            int m = g >> 3, k4 = g & 7;
            float4 av = *(const float4*)(Ab + (size_t)m * DH + kk + k4 * 4);
            As[k4*4+0][m] = av.x; As[k4*4+1][m] = av.y;
            As[k4*4+2][m] = av.z; As[k4*4+3][m] = av.w;
        }
        #pragma unroll
        for (int u = 0; u < 4; u++) {
            int g = u * 256 + tid;
            int m = g >> 3, k4 = g & 7;
            float4 bv = *(const float4*)(Bb + (size_t)m * DH + kk + k4 * 4);
            Bs[k4*4+0][m] = bv.x; Bs[k4*4+1][m] = bv.y;
            Bs[k4*4+2][m] = bv.z; Bs[k4*4+3][m] = bv.w;
        }
        __syncthreads();
        #pragma unroll
        for (int k = 0; k < 32; k++) {
            float a[8], b[8];
            *(float4*)&a[0] = *(const float4*)&As[k][ty*8];
            *(float4*)&a[4] = *(const float4*)&As[k][ty*8+4];
            *(float4*)&b[0] = *(const float4*)&Bs[k][tx*8];
            *(float4*)&b[4] = *(const float4*)&Bs[k][tx*8+4];
            #pragma unroll
            for (int i = 0; i < 8; i++)
                #pragma unroll
                for (int j = 0; j < 8; j++)
                    acc[i][j] += a[i] * b[j];
        }
        __syncthreads();
    }
    #pragma unroll
    for (int i = 0; i < 8; i++) {
        size_t r = (size_t)(m0 + ty * 8 + i) * MM + n0 + tx * 8;
        *(float4*)(Cb + r)     = make_float4(acc[i][0], acc[i][1], acc[i][2], acc[i][3]);
        *(float4*)(Cb + r + 4) = make_float4(acc[i][4], acc[i][5], acc[i][6], acc[i][7]);
    }
}

// ---------------------------------------------------------------------------
// Softmax over 256-wide rows (attn2), one block per row
// ---------------------------------------------------------------------------
__global__ __launch_bounds__(256) void softmax256() {
    int row = blockIdx.x, tid = threadIdx.x;
    float* p = g_attn2 + (size_t)row * MM;
    float v = p[tid];
    __shared__ float red[8];
    float m = v;
    #pragma unroll
    for (int o = 16; o; o >>= 1) m = fmaxf(m, __shfl_xor_sync(~0u, m, o));
    if ((tid & 31) == 0) red[tid >> 5] = m;
    __syncthreads();
    if (tid < 32) {
        float t = (tid < 8) ? red[tid] : -1e30f;
        #pragma unroll
        for (int o = 4; o; o >>= 1) t = fmaxf(t, __shfl_xor_sync(~0u, t, o));
        if (tid == 0) red[0] = t;
    }
    __syncthreads();
    float mx = red[0];
    __syncthreads();
    float e = __expf(v - mx);
    float s = e;
    #pragma unroll
    for (int o = 16; o; o >>= 1) s += __shfl_xor_sync(~0u, s, o);
    if ((tid & 31) == 0) red[tid >> 5] = s;
    __syncthreads();
    if (tid < 32) {
        float t = (tid < 8) ? red[tid] : 0.f;
        #pragma unroll
        for (int o = 4; o; o >>= 1) t += __shfl_xor_sync(~0u, t, o);
        if (tid == 0) red[0] = t;
    }
    __syncthreads();
    p[tid] = e / red[0];
}

// ---------------------------------------------------------------------------
// Softmax over 8192-wide bf16 rows (g_h3), in place
// ---------------------------------------------------------------------------
__global__ __launch_bounds__(256) void softmax8192bf() {
    int row = blockIdx.x, tid = threadIdx.x;
    uint4* p = (uint4*)(g_h3 + (size_t)row * NN);
    uint4 u[4];
    float f[32];
    float mx = -1e30f;
    #pragma unroll
    for (int i = 0; i < 4; i++) {
        u[i] = p[tid + i * 256];
        const uint32_t* w = (const uint32_t*)&u[i];
        #pragma unroll
        for (int j = 0; j < 4; j++) {
            float2 d = __bfloat1622float2(*(const __nv_bfloat162*)&w[j]);
            f[i*8 + j*2]     = d.x;
            f[i*8 + j*2 + 1] = d.y;
            mx = fmaxf(mx, fmaxf(d.x, d.y));
        }
    }
    __shared__ float red[8];
    #pragma unroll
    for (int o = 16; o; o >>= 1) mx = fmaxf(mx, __shfl_xor_sync(~0u, mx, o));
    if ((tid & 31) == 0) red[tid >> 5] = mx;
    __syncthreads();
    if (tid < 32) {
        float t = (tid < 8) ? red[tid] : -1e30f;
        #pragma unroll
        for (int o = 4; o; o >>= 1) t = fmaxf(t, __shfl_xor_sync(~0u, t, o));
        if (tid == 0) red[0] = t;
    }
    __syncthreads();
    float MX = red[0];
    __syncthreads();
    float s = 0.f;
    #pragma unroll
    for (int i = 0; i < 32; i++) { f[i] = __expf(f[i] - MX); s += f[i]; }
    #pragma unroll
    for (int o = 16; o; o >>= 1) s += __shfl_xor_sync(~0u, s, o);
    if ((tid & 31) == 0) red[tid >> 5] = s;
    __syncthreads();
    if (tid < 32) {
        float t = (tid < 8) ? red[tid] : 0.f;
        #pragma unroll
        for (int o = 4; o; o >>= 1) t += __shfl_xor_sync(~0u, t, o);
        if (tid == 0) red[0] = t;
    }
    __syncthreads();
    float inv = 1.f / red[0];
    #pragma unroll
    for (int i = 0; i < 4; i++) {
        uint32_t* w = (uint32_t*)&u[i];
        #pragma unroll
        for (int j = 0; j < 4; j++)
            w[j] = f2bf2(f[i*8 + j*2] * inv, f[i*8 + j*2 + 1] * inv);
        p[tid + i * 256] = u[i];
    }
}

// ---------------------------------------------------------------------------
// pinv init
// ---------------------------------------------------------------------------
__global__ void init_max_kernel() { g_maxA = 0; g_maxB = 0; }

__global__ __launch_bounds__(256) void colrowmax_kernel() {
    int bh = blockIdx.x, tid = threadIdx.x;
    const float* a = g_attn2 + (size_t)bh * MM * MM;
    float cs = 0.f, rs = 0.f;
    for (int m = 0; m < MM; m++) cs += fabsf(a[(size_t)m * MM + tid]);
    for (int n = 0; n < MM; n++) rs += fabsf(a[(size_t)tid * MM + n]);
    __shared__ float r1[8], r2[8];
    #pragma unroll
    for (int o = 16; o; o >>= 1) {
        cs = fmaxf(cs, __shfl_xor_sync(~0u, cs, o));
        rs = fmaxf(rs, __shfl_xor_sync(~0u, rs, o));
    }
    if ((tid & 31) == 0) { r1[tid >> 5] = cs; r2[tid >> 5] = rs; }
    __syncthreads();
    if (tid == 0) {
        float a1 = r1[0], a2 = r2[0];
        #pragma unroll
        for (int i = 1; i < 8; i++) { a1 = fmaxf(a1, r1[i]); a2 = fmaxf(a2, r2[i]); }
        atomicMax(&g_maxA, __float_as_int(a1));
        atomicMax(&g_maxB, __float_as_int(a2));
    }
}

__global__ __launch_bounds__(256) void z0_kernel() {
    int bh = blockIdx.z;
    int c0 = blockIdx.x * 32, r0 = blockIdx.y * 32;
    int tid = threadIdx.x;
    __shared__ float t[32][33];
    const float* a = g_attn2 + (size_t)bh * MM * MM;
    #pragma unroll
    for (int rr = 0; rr < 4; rr++) {
        int r = rr * 8 + (tid >> 5), c = tid & 31;
        t[r][c] = a[(size_t)(r0 + r) * MM + c0 + c];
    }
    __syncthreads();
    float s = 1.f / (__int_as_float(g_maxA) * __int_as_float(g_maxB));
    float* z = g_z + (size_t)bh * MM * MM;
    #pragma unroll
    for (int rr = 0; rr < 4; rr++) {
        int r = rr * 8 + (tid >> 5), c = tid & 31;
        z[(size_t)(c0 + r) * MM + r0 + c] = t[c][r] * s;
    }
}

// ---------------------------------------------------------------------------
// FFMA batched 256x256 (final pinv iteration)
// ---------------------------------------------------------------------------
__global__ __launch_bounds__(256) void matmul_ba128(const float* __restrict__ P,
                                                    const float* __restrict__ Q,
                                                    const float* __restrict__ R,
                                                    float* __restrict__ C,
                                                    float alpha, float beta) {
    __shared__ float As[16][132];
    __shared__ float Bs[16][132];
    size_t base = (size_t)blockIdx.z * (MM * MM);
    int m0 = blockIdx.y * 128, n0 = blockIdx.x * 128;
    int tid = threadIdx.x;
    int tx = tid & 15, ty = tid >> 4;
    float acc[8][8] = {};
    for (int kk = 0; kk < 256; kk += 16) {
        #pragma unroll
        for (int u = 0; u < 2; u++) {
            int g = u * 256 + tid;
            int m = g >> 2, k4 = g & 3;
            float4 av = *(const float4*)(P + base + (size_t)(m0 + m) * MM + kk + k4 * 4);
            As[k4*4+0][m] = av.x; As[k4*4+1][m] = av.y;
            As[k4*4+2][m] = av.z; As[k4*4+3][m] = av.w;
        }
        #pragma unroll
        for (int u = 0; u < 2; u++) {
            int g = u * 256 + tid;
            int k = g >> 5, n4 = g & 31;
            *(float4*)&Bs[k][n4*4] =
                *(const float4*)(Q + base + (size_t)(kk + k) * MM + n0 + n4 * 4);
        }
        __syncthreads();
        #pragma unroll
        for (int k = 0; k < 16; k++) {
            float a[8], b[8];
            *(float4*)&a[0] = *(const float4*)&As[k][ty*8];
            *(float4*)&a[4] = *(const float4*)&As[k][ty*8+4];
            *(float4*)&b[0] = *(const float4*)&Bs[k][tx*8];
            *(float4*)&b[4] = *(const float4*)&Bs[k][tx*8+4];
            #pragma unroll
            for (int i = 0; i < 8; i++)
                #pragma unroll
                for (int j = 0; j < 8; j++)
                    acc[i][j] += a[i] * b[j];
        }
        __syncthreads();
    }
    #pragma unroll
    for (int i = 0; i < 8; i++) {
        #pragma unroll
        for (int jj = 0; jj < 2; jj++) {
            size_t off = base + (size_t)(m0 + ty * 8 + i) * MM + n0 + tx * 8 + jj * 4;
            float4 rv = make_float4(0.f, 0.f, 0.f, 0.f);
            if (beta != 0.f) rv = *(const float4*)(R + off);
            float4 o;
            o.x = alpha * acc[i][jj*4+0] + beta * rv.x;
            o.y = alpha * acc[i][jj*4+1] + beta * rv.y;
            o.z = alpha * acc[i][jj*4+2] + beta * rv.z;
            o.w = alpha * acc[i][jj*4+3] + beta * rv.w;
            *(float4*)(C + off) = o;
        }
    }
}

// ---------------------------------------------------------------------------
// reduce k-split partials of attn3@v
// ---------------------------------------------------------------------------
__global__ __launch_bounds__(256) void reduce_p3() {
    size_t t = (size_t)blockIdx.x * 256 + threadIdx.x;
    size_t bh = t >> 14, rem = t & 16383;
    float s = 0.f;
    #pragma unroll
    for (int ks = 0; ks < KS; ks++)
        s += g_p3[((bh * KS + ks) << 14) + rem];
    g_out3[t] = s;
}

// ---------------------------------------------------------------------------
// Depthwise conv-33 residual of v -> y
// ---------------------------------------------------------------------------
__global__ __launch_bounds__(256) void conv_kernel(const float* __restrict__ res_w) {
    __shared__ float sv[160][64];
    __shared__ float sw[33];
    int bh = blockIdx.y, n0 = blockIdx.x * 128;
    int b = bh >> 3, h = bh & 7;
    int tid = threadIdx.x;
    if (tid < 33) sw[tid] = res_w[h * 33 + tid];
    const float* vb = g_v + (size_t)bh * NN * DH;
    #pragma unroll
    for (int i = 0; i < 10; i++) {
        int idx = tid + i * 256;
        int r = idx >> 4, c4 = idx & 15;
        int tok = n0 - 16 + r;
        float4 val = make_float4(0.f, 0.f, 0.f, 0.f);
        if (tok >= 0 && tok < NN)
            val = *(const float4*)(vb + (size_t)tok * DH + c4 * 4);
        *(float4*)&sv[r][c4 * 4] = val;
    }
    __syncthreads();
    #pragma unroll
    for (int i = 0; i < 8; i++) {
        int idx = tid + i * 256;
        int nl = idx >> 4, dg = idx & 15;
        float4 acc = make_float4(0.f, 0.f, 0.f, 0.f);
        #pragma unroll
        for (int j = 0; j < 33; j++) {
            float w = sw[j];
            float4 vv = *(const float4*)&sv[nl + j][dg * 4];
            acc.x += w * vv.x; acc.y += w * vv.y;
            acc.z += w * vv.z; acc.w += w * vv.w;
        }
        *(float4*)(g_y + ((size_t)b * NN + n0 + nl) * DD + h * 64 + dg * 4) = acc;
    }
}

// ---------------------------------------------------------------------------
// Launch
// ---------------------------------------------------------------------------
extern "C" void kernel_launch(void* const* d_in, const int* in_sizes, int n_in,
                              void* d_out, int out_size) {
    const float* x     = (const float*)d_in[0];
    const float* ln_w  = (const float*)d_in[1];
    const float* ln_b  = (const float*)d_in[2];
    const float* w_qkv = (const float*)d_in[3];
    const float* w_out = (const float*)d_in[4];
    const float* b_out = (const float*)d_in[5];
    const float* res_w = (const float*)d_in[6];
    float* out = (float*)d_out;

    float *p_xn, *p_q, *p_k, *p_v, *p_ql, *p_kl, *p_attn2;
    float *p_z, *p_z2, *p_xz, *p_t, *p_u;
    float *p_p3, *p_out3, *p_wc, *p_y;
    void *p_h3, *p_h1;
    cudaGetSymbolAddress((void**)&p_xn, g_xn);
    cudaGetSymbolAddress((void**)&p_q,  g_q);
    cudaGetSymbolAddress((void**)&p_k,  g_k);
    cudaGetSymbolAddress((void**)&p_v,  g_v);
    cudaGetSymbolAddress((void**)&p_ql, g_ql);
    cudaGetSymbolAddress((void**)&p_kl, g_kl);
    cudaGetSymbolAddress((void**)&p_attn2, g_attn2);
    cudaGetSymbolAddress((void**)&p_z,  g_z);
    cudaGetSymbolAddress((void**)&p_z2, g_z2);
    cudaGetSymbolAddress((void**)&p_xz, g_xz);
    cudaGetSymbolAddress((void**)&p_t,  g_t);
    cudaGetSymbolAddress((void**)&p_u,  g_u);
    cudaGetSymbolAddress(&p_h3, g_h3);
    cudaGetSymbolAddress(&p_h1, g_h1);
    cudaGetSymbolAddress((void**)&p_p3, g_p3);
    cudaGetSymbolAddress((void**)&p_out3, g_out3);
    cudaGetSymbolAddress((void**)&p_wc, g_wc);
    cudaGetSymbolAddress((void**)&p_y,  g_y);

    // LN -> QKV (bf16) -> landmarks
    ln_kernel<<<BB * NN, 128>>>(x, ln_w, ln_b);
    bf_gemm<0,128,128,32,false,false><<<dim3(12, 256, 1), 256>>>(
        p_xn, w_qkv, nullptr, nullptr, nullptr,
        1536, 512, 512, 1536, 0, 0, 0);
    landmark_kernel<<<dim3(MM, BH), 64>>>();

    // sim2 (fp32); sim3 -> bf16 scores; sim1 fused softmax -> bf16 probs
    gemm_sim2<<<dim3(2, 2, BH), 256>>>();
    bf_gemm<6,128,128,32,true,false><<<dim3(64, 2, BH), 256>>>(
        p_ql, p_k, p_h3, nullptr, nullptr,
        NN, 64, 64, 64, (long long)MM*DH, (long long)NN*DH, (long long)MM*NN);
    sim1_fused<<<dim3(1, 128, BH), 256>>>();

    // softmaxes
    softmax256<<<BH * MM, 256>>>();        // attn2 (f32)
    softmax8192bf<<<BH * MM, 256>>>();     // attn3 (bf16 in place)

    // pinv
    init_max_kernel<<<1, 1>>>();
    colrowmax_kernel<<<BH, 256>>>();
    z0_kernel<<<dim3(8, 8, BH), 256>>>();

    dim3 gba(2, 2, BH);
    float *zc = p_z, *zn = p_z2;
    for (int it = 0; it < 5; it++) {   // iterations 0..4 in tf32
        tc_gemm<4,128,128,32,false><<<gba, 256>>>(p_attn2, zc, p_xz, nullptr,
            MM, 256, 256, 256, (long long)MM*MM, (long long)MM*MM, (long long)MM*MM, 1.f, 0.f);
        tc_gemm<4,128,128,32,false><<<gba, 256>>>(p_xz, p_xz, p_t, p_xz,
            MM, 256, 256, 256, (long long)MM*MM, (long long)MM*MM, (long long)MM*MM, -1.f, 7.f);
        tc_gemm<4,128,128,32,false><<<gba, 256>>>(p_xz, p_t, p_u, p_xz,
            MM, 256, 256, 256, (long long)MM*MM, (long long)MM*MM, (long long)MM*MM, -1.f, 15.f);
        tc_gemm<4,128,128,32,false><<<gba, 256>>>(zc, p_u, zn, zc,
            MM, 256, 256, 256, (long long)MM*MM, (long long)MM*MM, (long long)MM*MM, -0.25f, 3.25f);
        float* tmp = zc; zc = zn; zn = tmp;
    }
    // final iteration in fp32 FFMA
    matmul_ba128<<<gba, 256>>>(p_attn2, zc, nullptr, p_xz, 1.f, 0.f);
    matmul_ba128<<<gba, 256>>>(p_xz, p_xz, p_xz, p_t, -1.f, 7.f);
    matmul_ba128<<<gba, 256>>>(p_xz, p_t, p_xz, p_u, -1.f, 15.f);
    matmul_ba128<<<gba, 256>>>(zc, p_u, zc, zn, -0.25f, 3.25f);
    { float* tmp = zc; zc = zn; zn = tmp; }

    // out3 = attn3 @ v (bf16 A, k-split 16) then reduce
    bf_gemm<3,128,64,32,false,true><<<dim3(1, 2, BH * KS), 256>>>(
        p_h3, p_v, p_p3, nullptr, nullptr,
        64, 512, NN, 64, 0, 0, 0);
    reduce_p3<<<2048, 256>>>();

    // Wc = z_final @ out3 (tf32)
    tc_gemm<2,128,64,32,false><<<dim3(1, 2, BH), 256>>>(
        zc, p_out3, p_wc, nullptr,
        64, 256, 256, 64, (long long)MM*MM, (long long)MM*DH, (long long)MM*DH, 0.f, 0.f);

    // y = conv residual ; y += attn1 @ Wc (bf16 A)
    conv_kernel<<<dim3(64, BH), 256>>>(res_w);
    bf_gemm<5,128,64,32,false,true><<<dim3(1, 64, BH), 256>>>(
        p_h1, p_wc, p_y, nullptr, nullptr,
        64, 256, 256, 64, (long long)NN*MM, (long long)MM*DH, 0);

    // out = y @ w_out + b_out + x (bf16)
    bf_gemm<1,128,128,32,false,false><<<dim3(4, 256, 1), 256>>>(
        p_y, w_out, out, b_out, x,
        512, 512, 512, 512, 0, 0, 0);
}

// round 7
// speedup vs baseline: 2.2455x; 1.0025x over previous
#include <cuda_runtime.h>
#include <cuda_bf16.h>
#include <stdint.h>
#include <math.h>

// ---------------------------------------------------------------------------
// Constants: B=4, N=8192, DIM=512, HEADS=8, DH=64, M=256 landmarks, l=32
// ---------------------------------------------------------------------------
#define BB 4
#define NN 8192
#define DD 512
#define HH 8
#define DH 64
#define MM 256
#define BH 32
#define KS 16   /* k-split for attn3@v */

// ---------------------------------------------------------------------------
// Scratch (device globals; allocation is forbidden)
// ---------------------------------------------------------------------------
__device__ __align__(16) float g_xn  [(size_t)BB*NN*DD];
__device__ __align__(16) float g_q   [(size_t)BH*NN*DH];
__device__ __align__(16) float g_k   [(size_t)BH*NN*DH];
__device__ __align__(16) float g_v   [(size_t)BH*NN*DH];
__device__ __align__(16) float g_ql  [(size_t)BH*MM*DH];
__device__ __align__(16) float g_kl  [(size_t)BH*MM*DH];
__device__ __align__(16) float g_attn2[(size_t)BH*MM*MM];
__device__ __align__(16) float g_z   [(size_t)BH*MM*MM];
__device__ __align__(16) float g_z2  [(size_t)BH*MM*MM];
__device__ __align__(16) float g_xz  [(size_t)BH*MM*MM];
__device__ __align__(16) float g_t   [(size_t)BH*MM*MM];
__device__ __align__(16) float g_u   [(size_t)BH*MM*MM];
__device__ __align__(16) __nv_bfloat16 g_h3[(size_t)BH*MM*NN];  // attn3 scores/probs bf16
__device__ __align__(16) __nv_bfloat16 g_h1[(size_t)BH*NN*MM];  // attn1 probs bf16
__device__ __align__(16) float g_p3  [(size_t)BH*KS*MM*DH];
__device__ __align__(16) float g_out3[(size_t)BH*MM*DH];
__device__ __align__(16) float g_wc  [(size_t)BH*MM*DH];
__device__ __align__(16) float g_y   [(size_t)BB*NN*DD];
__device__ int g_maxA;
__device__ int g_maxB;

// ---------------------------------------------------------------------------
// Conversion helpers
// ---------------------------------------------------------------------------
__device__ __forceinline__ uint32_t f2tf(float f) {
    uint32_t u;
    asm("cvt.rna.tf32.f32 %0, %1;" : "=r"(u) : "f"(f));
    return u;
}
// pack (lo,hi) floats -> bf16x2 with lo in low 16 bits
__device__ __forceinline__ uint32_t f2bf2(float lo, float hi) {
    uint32_t r;
    asm("cvt.rn.bf16x2.f32 %0, %1, %2;" : "=r"(r) : "f"(hi), "f"(lo));
    return r;
}

__device__ __forceinline__ void mma8(float* d, const uint32_t* a, const uint32_t* b) {
    asm volatile(
        "mma.sync.aligned.m16n8k8.row.col.f32.tf32.tf32.f32 "
        "{%0,%1,%2,%3}, {%4,%5,%6,%7}, {%8,%9}, {%0,%1,%2,%3};"
        : "+f"(d[0]), "+f"(d[1]), "+f"(d[2]), "+f"(d[3])
        : "r"(a[0]), "r"(a[1]), "r"(a[2]), "r"(a[3]), "r"(b[0]), "r"(b[1]));
}
__device__ __forceinline__ void mma16(float* d, const uint32_t* a, const uint32_t* b) {
    asm volatile(
        "mma.sync.aligned.m16n8k16.row.col.f32.bf16.bf16.f32 "
        "{%0,%1,%2,%3}, {%4,%5,%6,%7}, {%8,%9}, {%0,%1,%2,%3};"
        : "+f"(d[0]), "+f"(d[1]), "+f"(d[2]), "+f"(d[3])
        : "r"(a[0]), "r"(a[1]), "r"(a[2]), "r"(a[3]), "r"(b[0]), "r"(b[1]));
}

// ---------------------------------------------------------------------------
// TF32 tensor-core GEMM (pinv + Wc): 256 thr, 8 warps (2m x 4n)
// EPI: 2=plain batched store  4=alpha*(PQ)+beta*R batched
// ---------------------------------------------------------------------------
template<int EPI, int BM, int BN, int BK, bool TRB>
__global__ __launch_bounds__(256) void tc_gemm(
    const float* __restrict__ A, const float* __restrict__ Bg,
    float* __restrict__ C, const float* __restrict__ X1,
    int N, int K, int lda, int ldb,
    long long bsA, long long bsB, long long bsC,
    float alpha, float beta)
{
    constexpr int PA = BM + 8, PB = BN + 8;
    constexpr int MT = (BM / 2) / 16;
    constexpr int NT = (BN / 4) / 8;
    __shared__ uint32_t As[BK][PA];
    __shared__ uint32_t Bs[BK][PB];

    int tid = threadIdx.x, lane = tid & 31, warp = tid >> 5;
    int wm0 = (warp >> 2) * (BM / 2);
    int wn0 = (warp & 3) * (BN / 4);
    int z = blockIdx.z;
    int m0 = blockIdx.y * BM, n0 = blockIdx.x * BN;

    const float* Ab = A  + (size_t)z * bsA;
    const float* Bb = Bg + (size_t)z * bsB;

    float acc[MT][NT][4];
    #pragma unroll
    for (int i = 0; i < MT; i++)
        #pragma unroll
        for (int j = 0; j < NT; j++)
            #pragma unroll
            for (int r = 0; r < 4; r++) acc[i][j][r] = 0.f;

    for (int k0 = 0; k0 < K; k0 += BK) {
        #pragma unroll
        for (int c = 0; c < (BM * BK) / 1024; c++) {
            int id = c * 256 + tid;
            int m  = id / (BK / 4);
            int kq = id % (BK / 4);
            float4 v = *(const float4*)(Ab + (size_t)(m0 + m) * lda + k0 + kq * 4);
            As[kq*4+0][m] = f2tf(v.x); As[kq*4+1][m] = f2tf(v.y);
            As[kq*4+2][m] = f2tf(v.z); As[kq*4+3][m] = f2tf(v.w);
        }
        if constexpr (!TRB) {
            #pragma unroll
            for (int c = 0; c < (BK * BN) / 1024; c++) {
                int id = c * 256 + tid;
                int k  = id / (BN / 4);
                int nq = id % (BN / 4);
                float4 v = *(const float4*)(Bb + (size_t)(k0 + k) * ldb + n0 + nq * 4);
                Bs[k][nq*4+0] = f2tf(v.x); Bs[k][nq*4+1] = f2tf(v.y);
                Bs[k][nq*4+2] = f2tf(v.z); Bs[k][nq*4+3] = f2tf(v.w);
            }
        } else {
            #pragma unroll
            for (int c = 0; c < (BN * BK) / 1024; c++) {
                int id = c * 256 + tid;
                int n  = id / (BK / 4);
                int kq = id % (BK / 4);
                float4 v = *(const float4*)(Bb + (size_t)(n0 + n) * ldb + k0 + kq * 4);
                Bs[kq*4+0][n] = f2tf(v.x); Bs[kq*4+1][n] = f2tf(v.y);
                Bs[kq*4+2][n] = f2tf(v.z); Bs[kq*4+3][n] = f2tf(v.w);
            }
        }
        __syncthreads();
        #pragma unroll
        for (int ks = 0; ks < BK / 8; ks++) {
            uint32_t af[MT][4], bf[NT][2];
            int kr = ks * 8 + (lane & 3);
            int mr = wm0 + (lane >> 2);
            #pragma unroll
            for (int mt = 0; mt < MT; mt++) {
                af[mt][0] = As[kr    ][mr + mt * 16];
                af[mt][1] = As[kr    ][mr + mt * 16 + 8];
                af[mt][2] = As[kr + 4][mr + mt * 16];
                af[mt][3] = As[kr + 4][mr + mt * 16 + 8];
            }
            int nr = wn0 + (lane >> 2);
            #pragma unroll
            for (int nt = 0; nt < NT; nt++) {
                bf[nt][0] = Bs[kr    ][nr + nt * 8];
                bf[nt][1] = Bs[kr + 4][nr + nt * 8];
            }
            #pragma unroll
            for (int mt = 0; mt < MT; mt++)
                #pragma unroll
                for (int nt = 0; nt < NT; nt++)
                    mma8(acc[mt][nt], af[mt], bf[nt]);
        }
        __syncthreads();
    }

    #pragma unroll
    for (int mt = 0; mt < MT; mt++) {
        #pragma unroll
        for (int nt = 0; nt < NT; nt++) {
            int row = m0 + wm0 + mt * 16 + (lane >> 2);
            int col = n0 + wn0 + nt * 8 + (lane & 3) * 2;
            float2 lo = make_float2(acc[mt][nt][0], acc[mt][nt][1]);
            float2 hi = make_float2(acc[mt][nt][2], acc[mt][nt][3]);
            if constexpr (EPI == 2) {
                size_t base = (size_t)z * bsC;
                *(float2*)(C + base + (size_t)row       * N + col) = lo;
                *(float2*)(C + base + (size_t)(row + 8) * N + col) = hi;
            } else if constexpr (EPI == 4) {
                size_t base = (size_t)z * (MM * MM);
                size_t r1 = base + (size_t)row * MM + col;
                size_t r2 = base + (size_t)(row + 8) * MM + col;
                float2 rv1 = make_float2(0.f, 0.f), rv2 = make_float2(0.f, 0.f);
                if (beta != 0.f) {
                    rv1 = *(const float2*)(X1 + r1);
                    rv2 = *(const float2*)(X1 + r2);
                }
                *(float2*)(C + r1) = make_float2(alpha*lo.x + beta*rv1.x, alpha*lo.y + beta*rv1.y);
                *(float2*)(C + r2) = make_float2(alpha*hi.x + beta*rv2.x, alpha*hi.y + beta*rv2.y);
            }
        }
    }
}

// ---------------------------------------------------------------------------
// BF16 tensor-core GEMM (m16n8k16), 256 thr, 8 warps (2m x 4n)
// EPI: 0=QKV scatter  1=out+bias+x  3=p3 partial (k-split via z)
//      5=y += scatter  6=bf16 plain batched store
// BFA: A operand already bf16 in gmem; TRB: B is [N,K] f32 row-major
// ---------------------------------------------------------------------------
template<int EPI, int BM, int BN, int BK, bool TRB, bool BFA>
__global__ __launch_bounds__(256) void bf_gemm(
    const void* __restrict__ Av, const float* __restrict__ Bg,
    void* __restrict__ Cv, const float* __restrict__ X1, const float* __restrict__ X2,
    int N, int K, int lda, int ldb,
    long long bsA, long long bsB, long long bsC)
{
    constexpr int PA = BM + 8, PB = BN + 8;
    constexpr int MT = (BM / 2) / 16;
    constexpr int NT = (BN / 4) / 8;
    __shared__ uint32_t As[BK/2][PA];
    __shared__ uint32_t Bs[BK/2][PB];

    int tid = threadIdx.x, lane = tid & 31, warp = tid >> 5;
    int wm0 = (warp >> 2) * (BM / 2);
    int wn0 = (warp & 3) * (BN / 4);
    int z = blockIdx.z;
    int m0 = blockIdx.y * BM, n0 = blockIdx.x * BN;

    const float* Bb;
    const float* Abf = nullptr;
    const __nv_bfloat16* Abh = nullptr;
    if constexpr (EPI == 3) {
        int bh = z >> 4, ks = z & 15;
        Abh = (const __nv_bfloat16*)Av + (size_t)bh * MM * NN + (size_t)ks * 512;
        Bb  = Bg + (size_t)bh * NN * DH + (size_t)ks * 512 * DH;
    } else {
        if constexpr (BFA) Abh = (const __nv_bfloat16*)Av + (size_t)z * bsA;
        else               Abf = (const float*)Av + (size_t)z * bsA;
        Bb = Bg + (size_t)z * bsB;
    }
    if constexpr (EPI == 3 && !BFA) { /* unreachable */ }

    float acc[MT][NT][4];
    #pragma unroll
    for (int i = 0; i < MT; i++)
        #pragma unroll
        for (int j = 0; j < NT; j++)
            #pragma unroll
            for (int r = 0; r < 4; r++) acc[i][j][r] = 0.f;

    for (int k0 = 0; k0 < K; k0 += BK) {
        // ---- A tile
        if constexpr (BFA || EPI == 3) {
            #pragma unroll
            for (int c = 0; c < (BM * BK) / 2048; c++) {
                int id = c * 256 + tid;
                int m  = id / (BK / 8);
                int kq = id % (BK / 8);
                uint4 v = *(const uint4*)(Abh + (size_t)(m0 + m) * lda + k0 + kq * 8);
                As[kq*4+0][m] = v.x; As[kq*4+1][m] = v.y;
                As[kq*4+2][m] = v.z; As[kq*4+3][m] = v.w;
            }
        } else {
            #pragma unroll
            for (int c = 0; c < (BM * BK) / 1024; c++) {
                int id = c * 256 + tid;
                int m  = id / (BK / 4);
                int kq = id % (BK / 4);
                float4 v = *(const float4*)(Abf + (size_t)(m0 + m) * lda + k0 + kq * 4);
                As[kq*2+0][m] = f2bf2(v.x, v.y);
                As[kq*2+1][m] = f2bf2(v.z, v.w);
            }
        }
        // ---- B tile (f32 source)
        if constexpr (!TRB) {
            #pragma unroll
            for (int c = 0; c < (BK / 2) * (BN / 4) / 256; c++) {
                int id = c * 256 + tid;
                int kp = id / (BN / 4);
                int nq = id % (BN / 4);
                float4 lo = *(const float4*)(Bb + (size_t)(k0 + 2*kp    ) * ldb + n0 + nq * 4);
                float4 hi = *(const float4*)(Bb + (size_t)(k0 + 2*kp + 1) * ldb + n0 + nq * 4);
                Bs[kp][nq*4+0] = f2bf2(lo.x, hi.x);
                Bs[kp][nq*4+1] = f2bf2(lo.y, hi.y);
                Bs[kp][nq*4+2] = f2bf2(lo.z, hi.z);
                Bs[kp][nq*4+3] = f2bf2(lo.w, hi.w);
            }
        } else {
            #pragma unroll
            for (int c = 0; c < (BN * BK) / 1024; c++) {
                int id = c * 256 + tid;
                int n  = id / (BK / 4);
                int kq = id % (BK / 4);
                float4 v = *(const float4*)(Bb + (size_t)(n0 + n) * ldb + k0 + kq * 4);
                Bs[kq*2+0][n] = f2bf2(v.x, v.y);
                Bs[kq*2+1][n] = f2bf2(v.z, v.w);
            }
        }
        __syncthreads();
        #pragma unroll
        for (int ks = 0; ks < BK / 16; ks++) {
            uint32_t af[MT][4], bf[NT][2];
            int kr = ks * 8 + (lane & 3);
            int mr = wm0 + (lane >> 2);
            #pragma unroll
            for (int mt = 0; mt < MT; mt++) {
                af[mt][0] = As[kr    ][mr + mt * 16];
                af[mt][1] = As[kr    ][mr + mt * 16 + 8];
                af[mt][2] = As[kr + 4][mr + mt * 16];
                af[mt][3] = As[kr + 4][mr + mt * 16 + 8];
            }
            int nr = wn0 + (lane >> 2);
            #pragma unroll
            for (int nt = 0; nt < NT; nt++) {
                bf[nt][0] = Bs[kr    ][nr + nt * 8];
                bf[nt][1] = Bs[kr + 4][nr + nt * 8];
            }
            #pragma unroll
            for (int mt = 0; mt < MT; mt++)
                #pragma unroll
                for (int nt = 0; nt < NT; nt++)
                    mma16(acc[mt][nt], af[mt], bf[nt]);
        }
        __syncthreads();
    }

    #pragma unroll
    for (int mt = 0; mt < MT; mt++) {
        #pragma unroll
        for (int nt = 0; nt < NT; nt++) {
            int row = m0 + wm0 + mt * 16 + (lane >> 2);
            int col = n0 + wn0 + nt * 8 + (lane & 3) * 2;
            float2 lo = make_float2(acc[mt][nt][0], acc[mt][nt][1]);
            float2 hi = make_float2(acc[mt][nt][2], acc[mt][nt][3]);
            if constexpr (EPI == 0) {
                int which = col >> 9, inner = col & 511;
                int h = inner >> 6, d = inner & 63;
                float* dst = which == 0 ? g_q : (which == 1 ? g_k : g_v);
                float s = (which == 0) ? 0.125f : 1.f;
                int bq = row >> 13, n = row & (NN - 1);
                *(float2*)(dst + (((size_t)(bq*HH+h))*NN + n    )*DH + d) = make_float2(lo.x*s, lo.y*s);
                *(float2*)(dst + (((size_t)(bq*HH+h))*NN + n + 8)*DH + d) = make_float2(hi.x*s, hi.y*s);
            } else if constexpr (EPI == 1) {
                float* C = (float*)Cv;
                float2 bv = *(const float2*)(X1 + col);
                size_t r1 = (size_t)row * DD + col, r2 = (size_t)(row + 8) * DD + col;
                float2 x1 = *(const float2*)(X2 + r1);
                float2 x2 = *(const float2*)(X2 + r2);
                *(float2*)(C + r1) = make_float2(lo.x + bv.x + x1.x, lo.y + bv.y + x1.y);
                *(float2*)(C + r2) = make_float2(hi.x + bv.x + x2.x, hi.y + bv.y + x2.y);
            } else if constexpr (EPI == 3) {
                float* C = (float*)Cv;
                size_t base = (size_t)z * (MM * DH);
                *(float2*)(C + base + (row    ) * DH + col) = lo;
                *(float2*)(C + base + (row + 8) * DH + col) = hi;
            } else if constexpr (EPI == 5) {
                float* C = (float*)Cv;
                int b = z >> 3, h = z & 7;
                size_t r1 = ((size_t)b * NN + row    ) * DD + h * 64 + col;
                size_t r2 = ((size_t)b * NN + row + 8) * DD + h * 64 + col;
                float2 y1 = *(float2*)(C + r1);
                float2 y2 = *(float2*)(C + r2);
                *(float2*)(C + r1) = make_float2(y1.x + lo.x, y1.y + lo.y);
                *(float2*)(C + r2) = make_float2(y2.x + hi.x, y2.y + hi.y);
            } else if constexpr (EPI == 6) {
                __nv_bfloat16* C = (__nv_bfloat16*)Cv;
                size_t base = (size_t)z * bsC;
                *(uint32_t*)(C + base + (size_t)row       * N + col) = f2bf2(lo.x, lo.y);
                *(uint32_t*)(C + base + (size_t)(row + 8) * N + col) = f2bf2(hi.x, hi.y);
            }
        }
    }
}

// ---------------------------------------------------------------------------
// Fused sim1 + softmax: attn1 = softmax(q @ kl^T) rows of 256, bf16 out
// BM=64 rows/block, BN=256 (full row), K=64, 8 warps (2m x 4n)
// ---------------------------------------------------------------------------
__global__ __launch_bounds__(256) void sim1_fused() {
    __shared__ uint32_t As[16][72];    // K/2=16... per BK=32 chunk: 16 rows
    __shared__ uint32_t Bs[16][264];
    __shared__ float rmax[64][5];
    __shared__ float rsum[64][5];

    int tid = threadIdx.x, lane = tid & 31, warp = tid >> 5;
    int wm0 = (warp >> 2) * 32;        // 2 m-warps * 32 rows
    int wn0 = (warp & 3) * 64;         // 4 n-warps * 64 cols
    int bh = blockIdx.z;
    int m0 = blockIdx.y * 64;
    const float* Ab = g_q  + ((size_t)bh * NN + m0) * DH;
    const float* Bb = g_kl + (size_t)bh * MM * DH;

    float acc[2][8][4];
    #pragma unroll
    for (int i = 0; i < 2; i++)
        #pragma unroll
        for (int j = 0; j < 8; j++)
            #pragma unroll
            for (int r = 0; r < 4; r++) acc[i][j][r] = 0.f;

    for (int k0 = 0; k0 < 64; k0 += 32) {
        // A: 64 rows x 32 k -> 2048 f32 = 512 float4; 2 per thread
        #pragma unroll
        for (int c = 0; c < 2; c++) {
            int id = c * 256 + tid;
            int m = id >> 3, kq = id & 7;
            float4 v = *(const float4*)(Ab + (size_t)m * DH + k0 + kq * 4);
            As[kq*2+0][m] = f2bf2(v.x, v.y);
            As[kq*2+1][m] = f2bf2(v.z, v.w);
        }
        // B (TRB): 256 rows x 32 k -> 8 per thread
        #pragma unroll
        for (int c = 0; c < 8; c++) {
            int id = c * 256 + tid;
            int n = id >> 3, kq = id & 7;
            float4 v = *(const float4*)(Bb + (size_t)n * DH + k0 + kq * 4);
            Bs[kq*2+0][n] = f2bf2(v.x, v.y);
            Bs[kq*2+1][n] = f2bf2(v.z, v.w);
        }
        __syncthreads();
        #pragma unroll
        for (int ks = 0; ks < 2; ks++) {
            uint32_t af[2][4], bf[8][2];
            int kr = ks * 8 + (lane & 3);
            int mr = wm0 + (lane >> 2);
            #pragma unroll
            for (int mt = 0; mt < 2; mt++) {
                af[mt][0] = As[kr    ][mr + mt * 16];
                af[mt][1] = As[kr    ][mr + mt * 16 + 8];
                af[mt][2] = As[kr + 4][mr + mt * 16];
                af[mt][3] = As[kr + 4][mr + mt * 16 + 8];
            }
            int nr = wn0 + (lane >> 2);
            #pragma unroll
            for (int nt = 0; nt < 8; nt++) {
                bf[nt][0] = Bs[kr    ][nr + nt * 8];
                bf[nt][1] = Bs[kr + 4][nr + nt * 8];
            }
            #pragma unroll
            for (int mt = 0; mt < 2; mt++)
                #pragma unroll
                for (int nt = 0; nt < 8; nt++)
                    mma16(acc[mt][nt], af[mt], bf[nt]);
        }
        __syncthreads();
    }

    // ---- softmax over full 256-wide rows -----------------------------------
    int g = lane >> 2, q4 = lane & 3;
    int wn = warp & 3;
    // partial row max: each thread covers 16 cols of each of its 4 rows
    #pragma unroll
    for (int mt = 0; mt < 2; mt++) {
        int r0 = wm0 + mt * 16 + g;      // local row (lo half)
        float m0v = -1e30f, m1v = -1e30f;
        #pragma unroll
        for (int nt = 0; nt < 8; nt++) {
            m0v = fmaxf(m0v, fmaxf(acc[mt][nt][0], acc[mt][nt][1]));
            m1v = fmaxf(m1v, fmaxf(acc[mt][nt][2], acc[mt][nt][3]));
        }
        // reduce over quad (lane&3)
        #pragma unroll
        for (int o = 1; o < 4; o <<= 1) {
            m0v = fmaxf(m0v, __shfl_xor_sync(~0u, m0v, o));
            m1v = fmaxf(m1v, __shfl_xor_sync(~0u, m1v, o));
        }
        if (q4 == 0) { rmax[r0][wn] = m0v; rmax[r0 + 8][wn] = m1v; }
    }
    __syncthreads();
    // exp + partial sums
    #pragma unroll
    for (int mt = 0; mt < 2; mt++) {
        int r0 = wm0 + mt * 16 + g;
        float M0 = fmaxf(fmaxf(rmax[r0][0], rmax[r0][1]), fmaxf(rmax[r0][2], rmax[r0][3]));
        float M1 = fmaxf(fmaxf(rmax[r0+8][0], rmax[r0+8][1]), fmaxf(rmax[r0+8][2], rmax[r0+8][3]));
        float s0 = 0.f, s1 = 0.f;
        #pragma unroll
        for (int nt = 0; nt < 8; nt++) {
            acc[mt][nt][0] = __expf(acc[mt][nt][0] - M0);
            acc[mt][nt][1] = __expf(acc[mt][nt][1] - M0);
            acc[mt][nt][2] = __expf(acc[mt][nt][2] - M1);
            acc[mt][nt][3] = __expf(acc[mt][nt][3] - M1);
            s0 += acc[mt][nt][0] + acc[mt][nt][1];
            s1 += acc[mt][nt][2] + acc[mt][nt][3];
        }
        #pragma unroll
        for (int o = 1; o < 4; o <<= 1) {
            s0 += __shfl_xor_sync(~0u, s0, o);
            s1 += __shfl_xor_sync(~0u, s1, o);
        }
        if (q4 == 0) { rsum[r0][wn] = s0; rsum[r0 + 8][wn] = s1; }
    }
    __syncthreads();
    // normalize + bf16 store
    __nv_bfloat16* O = g_h1 + ((size_t)bh * NN + m0) * MM;
    #pragma unroll
    for (int mt = 0; mt < 2; mt++) {
        int r0 = wm0 + mt * 16 + g;
        float i0 = 1.f / (rsum[r0][0] + rsum[r0][1] + rsum[r0][2] + rsum[r0][3]);
        float i1 = 1.f / (rsum[r0+8][0] + rsum[r0+8][1] + rsum[r0+8][2] + rsum[r0+8][3]);
        #pragma unroll
        for (int nt = 0; nt < 8; nt++) {
            int col = wn0 + nt * 8 + q4 * 2;
            *(uint32_t*)(O + (size_t)r0 * MM + col) =
                f2bf2(acc[mt][nt][0] * i0, acc[mt][nt][1] * i0);
            *(uint32_t*)(O + (size_t)(r0 + 8) * MM + col) =
                f2bf2(acc[mt][nt][2] * i1, acc[mt][nt][3] * i1);
        }
    }
}

// ---------------------------------------------------------------------------
// LayerNorm
// ---------------------------------------------------------------------------
__global__ __launch_bounds__(128) void ln_kernel(const float* __restrict__ x,
                                                 const float* __restrict__ w,
                                                 const float* __restrict__ bia) {
    int row = blockIdx.x, tid = threadIdx.x;
    const float4* xr = reinterpret_cast<const float4*>(x + (size_t)row * DD);
    float4 v = xr[tid];
    float s  = v.x + v.y + v.z + v.w;
    float sq = v.x*v.x + v.y*v.y + v.z*v.z + v.w*v.w;
    __shared__ float sm[4], sm2[4];
    #pragma unroll
    for (int o = 16; o > 0; o >>= 1) {
        s  += __shfl_down_sync(0xffffffffu, s,  o);
        sq += __shfl_down_sync(0xffffffffu, sq, o);
    }
    if ((tid & 31) == 0) { sm[tid >> 5] = s; sm2[tid >> 5] = sq; }
    __syncthreads();
    if (tid == 0) {
        float a = 0.f, b2 = 0.f;
        #pragma unroll
        for (int i = 0; i < 4; i++) { a += sm[i]; b2 += sm2[i]; }
        sm[0] = a; sm2[0] = b2;
    }
    __syncthreads();
    float mean = sm[0] * (1.f / 512.f);
    float var  = sm2[0] * (1.f / 512.f) - mean * mean;
    float rstd = rsqrtf(var + 1e-5f);
    float4 wv = reinterpret_cast<const float4*>(w)[tid];
    float4 bv = reinterpret_cast<const float4*>(bia)[tid];
    float4 o;
    o.x = (v.x - mean) * rstd * wv.x + bv.x;
    o.y = (v.y - mean) * rstd * wv.y + bv.y;
    o.z = (v.z - mean) * rstd * wv.z + bv.z;
    o.w = (v.w - mean) * rstd * wv.w + bv.w;
    reinterpret_cast<float4*>(g_xn + (size_t)row * DD)[tid] = o;
}

// ---------------------------------------------------------------------------
// Landmarks
// ---------------------------------------------------------------------------
__global__ void landmark_kernel() {
    int m = blockIdx.x, bh = blockIdx.y;
    int d = threadIdx.x;
    size_t base = ((size_t)bh * NN + (size_t)m * 32) * DH + d;
    float sq = 0.f, sk = 0.f;
    #pragma unroll
    for (int j = 0; j < 32; j++) {
        sq += g_q[base + (size_t)j * DH];
        sk += g_k[base + (size_t)j * DH];
    }
    size_t o = ((size_t)bh * MM + m) * DH + d;
    g_ql[o] = sq * (1.f / 32.f);
    g_kl[o] = sk * (1.f / 32.f);
}

// ---------------------------------------------------------------------------
// sim2 (FFMA fp32, feeds pinv)
// ---------------------------------------------------------------------------
__global__ __launch_bounds__(256) void gemm_sim2() {
    __shared__ float As[32][132];
    __shared__ float Bs[32][132];
    int bh = blockIdx.z;
    int n0 = blockIdx.x * 128, m0 = blockIdx.y * 128;
    const float* Ab = g_ql + ((size_t)bh * MM + m0) * DH;
    const float* Bb = g_kl + ((size_t)bh * MM + n0) * DH;
    float* Cb = g_attn2 + (size_t)bh * MM * MM;
    int tid = threadIdx.x;
    int tx = tid & 15, ty = tid >> 4;
    float acc[8][8] = {};
    for (int kk = 0; kk < 64; kk += 32) {
        #pragma unroll
        for (int u = 0; u < 4; u++) {
            int g = u * 256 + tid;
            int m = g >> 3, k4 = g & 7;
            float4 av = *(const float4*)(Ab + (size_t)m * DH + kk + k4 * 4);
            As[k4*4+0][m] = av.x; As[k4*4+1][m] = av.y;
            As[k4*4+2][m] = av.z; As[k4*4+3][m] = av.w;
        }
        #pragma unroll
        for (int u = 0; u < 4; u++) {
            int g = u * 256 + tid;
            int m = g >> 3, k4 = g & 7;
            float4 bv = *(const float4*)(Bb + (size_t)m * DH + kk + k4 * 4);
            Bs[k4*4+0][m] = bv.x; Bs[k4*4+1][m] = bv.y;
            Bs[k4*4+2][m] = bv.z; Bs[k4*4+3][m] = bv.w;
        }
        __syncthreads();
        #pragma unroll
        for (int k = 0; k < 32; k++) {
            float a[8], b[8];
            *(float4*)&a[0] = *(const float4*)&As[k][ty*8];
            *(float4*)&a[4] = *(const float4*)&As[k][ty*8+4];
            *(float4*)&b[0] = *(const float4*)&Bs[k][tx*8];
            *(float4*)&b[4] = *(const float4*)&Bs[k][tx*8+4];
            #pragma unroll
            for (int i = 0; i < 8; i++)
                #pragma unroll
                for (int j = 0; j < 8; j++)
                    acc[i][j] += a[i] * b[j];
        }
        __syncthreads();
    }
    #pragma unroll
    for (int i = 0; i < 8; i++) {
        size_t r = (size_t)(m0 + ty * 8 + i) * MM + n0 + tx * 8;
        *(float4*)(Cb + r)     = make_float4(acc[i][0], acc[i][1], acc[i][2], acc[i][3]);
        *(float4*)(Cb + r + 4) = make_float4(acc[i][4], acc[i][5], acc[i][6], acc[i][7]);
    }
}

// ---------------------------------------------------------------------------
// Softmax over 256-wide rows (attn2), one block per row
// ---------------------------------------------------------------------------
__global__ __launch_bounds__(256) void softmax256() {
    int row = blockIdx.x, tid = threadIdx.x;
    float* p = g_attn2 + (size_t)row * MM;
    float v = p[tid];
    __shared__ float red[8];
    float m = v;
    #pragma unroll
    for (int o = 16; o; o >>= 1) m = fmaxf(m, __shfl_xor_sync(~0u, m, o));
    if ((tid & 31) == 0) red[tid >> 5] = m;
    __syncthreads();
    if (tid < 32) {
        float t = (tid < 8) ? red[tid] : -1e30f;
        #pragma unroll
        for (int o = 4; o; o >>= 1) t = fmaxf(t, __shfl_xor_sync(~0u, t, o));
        if (tid == 0) red[0] = t;
    }
    __syncthreads();
    float mx = red[0];
    __syncthreads();
    float e = __expf(v - mx);
    float s = e;
    #pragma unroll
    for (int o = 16; o; o >>= 1) s += __shfl_xor_sync(~0u, s, o);
    if ((tid & 31) == 0) red[tid >> 5] = s;
    __syncthreads();
    if (tid < 32) {
        float t = (tid < 8) ? red[tid] : 0.f;
        #pragma unroll
        for (int o = 4; o; o >>= 1) t += __shfl_xor_sync(~0u, t, o);
        if (tid == 0) red[0] = t;
    }
    __syncthreads();
    p[tid] = e / red[0];
}

// ---------------------------------------------------------------------------
// Softmax over 8192-wide bf16 rows (g_h3), in place
// ---------------------------------------------------------------------------
__global__ __launch_bounds__(256) void softmax8192bf() {
    int row = blockIdx.x, tid = threadIdx.x;
    uint4* p = (uint4*)(g_h3 + (size_t)row * NN);
    uint4 u[4];
    float f[32];
    float mx = -1e30f;
    #pragma unroll
    for (int i = 0; i < 4; i++) {
        u[i] = p[tid + i * 256];
        const uint32_t* w = (const uint32_t*)&u[i];
        #pragma unroll
        for (int j = 0; j < 4; j++) {
            float2 d = __bfloat1622float2(*(const __nv_bfloat162*)&w[j]);
            f[i*8 + j*2]     = d.x;
            f[i*8 + j*2 + 1] = d.y;
            mx = fmaxf(mx, fmaxf(d.x, d.y));
        }
    }
    __shared__ float red[8];
    #pragma unroll
    for (int o = 16; o; o >>= 1) mx = fmaxf(mx, __shfl_xor_sync(~0u, mx, o));
    if ((tid & 31) == 0) red[tid >> 5] = mx;
    __syncthreads();
    if (tid < 32) {
        float t = (tid < 8) ? red[tid] : -1e30f;
        #pragma unroll
        for (int o = 4; o; o >>= 1) t = fmaxf(t, __shfl_xor_sync(~0u, t, o));
        if (tid == 0) red[0] = t;
    }
    __syncthreads();
    float MX = red[0];
    __syncthreads();
    float s = 0.f;
    #pragma unroll
    for (int i = 0; i < 32; i++) { f[i] = __expf(f[i] - MX); s += f[i]; }
    #pragma unroll
    for (int o = 16; o; o >>= 1) s += __shfl_xor_sync(~0u, s, o);
    if ((tid & 31) == 0) red[tid >> 5] = s;
    __syncthreads();
    if (tid < 32) {
        float t = (tid < 8) ? red[tid] : 0.f;
        #pragma unroll
        for (int o = 4; o; o >>= 1) t += __shfl_xor_sync(~0u, t, o);
        if (tid == 0) red[0] = t;
    }
    __syncthreads();
    float inv = 1.f / red[0];
    #pragma unroll
    for (int i = 0; i < 4; i++) {
        uint32_t* w = (uint32_t*)&u[i];
        #pragma unroll
        for (int j = 0; j < 4; j++)
            w[j] = f2bf2(f[i*8 + j*2] * inv, f[i*8 + j*2 + 1] * inv);
        p[tid + i * 256] = u[i];
    }
}

// ---------------------------------------------------------------------------
// pinv init
// ---------------------------------------------------------------------------
__global__ void init_max_kernel() { g_maxA = 0; g_maxB = 0; }

__global__ __launch_bounds__(256) void colrowmax_kernel() {
    int bh = blockIdx.x, tid = threadIdx.x;
    const float* a = g_attn2 + (size_t)bh * MM * MM;
    float cs = 0.f, rs = 0.f;
    for (int m = 0; m < MM; m++) cs += fabsf(a[(size_t)m * MM + tid]);
    for (int n = 0; n < MM; n++) rs += fabsf(a[(size_t)tid * MM + n]);
    __shared__ float r1[8], r2[8];
    #pragma unroll
    for (int o = 16; o; o >>= 1) {
        cs = fmaxf(cs, __shfl_xor_sync(~0u, cs, o));
        rs = fmaxf(rs, __shfl_xor_sync(~0u, rs, o));
    }
    if ((tid & 31) == 0) { r1[tid >> 5] = cs; r2[tid >> 5] = rs; }
    __syncthreads();
    if (tid == 0) {
        float a1 = r1[0], a2 = r2[0];
        #pragma unroll
        for (int i = 1; i < 8; i++) { a1 = fmaxf(a1, r1[i]); a2 = fmaxf(a2, r2[i]); }
        atomicMax(&g_maxA, __float_as_int(a1));
        atomicMax(&g_maxB, __float_as_int(a2));
    }
}

__global__ __launch_bounds__(256) void z0_kernel() {
    int bh = blockIdx.z;
    int c0 = blockIdx.x * 32, r0 = blockIdx.y * 32;
    int tid = threadIdx.x;
    __shared__ float t[32][33];
    const float* a = g_attn2 + (size_t)bh * MM * MM;
    #pragma unroll
    for (int rr = 0; rr < 4; rr++) {
        int r = rr * 8 + (tid >> 5), c = tid & 31;
        t[r][c] = a[(size_t)(r0 + r) * MM + c0 + c];
    }
    __syncthreads();
    float s = 1.f / (__int_as_float(g_maxA) * __int_as_float(g_maxB));
    float* z = g_z + (size_t)bh * MM * MM;
    #pragma unroll
    for (int rr = 0; rr < 4; rr++) {
        int r = rr * 8 + (tid >> 5), c = tid & 31;
        z[(size_t)(c0 + r) * MM + r0 + c] = t[c][r] * s;
    }
}

// ---------------------------------------------------------------------------
// FFMA batched 256x256 (final pinv iteration)
// ---------------------------------------------------------------------------
__global__ __launch_bounds__(256) void matmul_ba128(const float* __restrict__ P,
                                                    const float* __restrict__ Q,
                                                    const float* __restrict__ R,
                                                    float* __restrict__ C,
                                                    float alpha, float beta) {
    __shared__ float As[16][132];
    __shared__ float Bs[16][132];
    size_t base = (size_t)blockIdx.z * (MM * MM);
    int m0 = blockIdx.y * 128, n0 = blockIdx.x * 128;
    int tid = threadIdx.x;
    int tx = tid & 15, ty = tid >> 4;
    float acc[8][8] = {};
    for (int kk = 0; kk < 256; kk += 16) {
        #pragma unroll
        for (int u = 0; u < 2; u++) {
            int g = u * 256 + tid;
            int m = g >> 2, k4 = g & 3;
            float4 av = *(const float4*)(P + base + (size_t)(m0 + m) * MM + kk + k4 * 4);
            As[k4*4+0][m] = av.x; As[k4*4+1][m] = av.y;
            As[k4*4+2][m] = av.z; As[k4*4+3][m] = av.w;
        }
        #pragma unroll
        for (int u = 0; u < 2; u++) {
            int g = u * 256 + tid;
            int k = g >> 5, n4 = g & 31;
            *(float4*)&Bs[k][n4*4] =
                *(const float4*)(Q + base + (size_t)(kk + k) * MM + n0 + n4 * 4);
        }
        __syncthreads();
        #pragma unroll
        for (int k = 0; k < 16; k++) {
            float a[8], b[8];
            *(float4*)&a[0] = *(const float4*)&As[k][ty*8];
            *(float4*)&a[4] = *(const float4*)&As[k][ty*8+4];
            *(float4*)&b[0] = *(const float4*)&Bs[k][tx*8];
            *(float4*)&b[4] = *(const float4*)&Bs[k][tx*8+4];
            #pragma unroll
            for (int i = 0; i < 8; i++)
                #pragma unroll
                for (int j = 0; j < 8; j++)
                    acc[i][j] += a[i] * b[j];
        }
        __syncthreads();
    }
    #pragma unroll
    for (int i = 0; i < 8; i++) {
        #pragma unroll
        for (int jj = 0; jj < 2; jj++) {
            size_t off = base + (size_t)(m0 + ty * 8 + i) * MM + n0 + tx * 8 + jj * 4;
            float4 rv = make_float4(0.f, 0.f, 0.f, 0.f);
            if (beta != 0.f) rv = *(const float4*)(R + off);
            float4 o;
            o.x = alpha * acc[i][jj*4+0] + beta * rv.x;
            o.y = alpha * acc[i][jj*4+1] + beta * rv.y;
            o.z = alpha * acc[i][jj*4+2] + beta * rv.z;
            o.w = alpha * acc[i][jj*4+3] + beta * rv.w;
            *(float4*)(C + off) = o;
        }
    }
}

// ---------------------------------------------------------------------------
// reduce k-split partials of attn3@v
// ---------------------------------------------------------------------------
__global__ __launch_bounds__(256) void reduce_p3() {
    size_t t = (size_t)blockIdx.x * 256 + threadIdx.x;
    size_t bh = t >> 14, rem = t & 16383;
    float s = 0.f;
    #pragma unroll
    for (int ks = 0; ks < KS; ks++)
        s += g_p3[((bh * KS + ks) << 14) + rem];
    g_out3[t] = s;
}

// ---------------------------------------------------------------------------
// Depthwise conv-33 residual of v -> y
// ---------------------------------------------------------------------------
__global__ __launch_bounds__(256) void conv_kernel(const float* __restrict__ res_w) {
    __shared__ float sv[160][64];
    __shared__ float sw[33];
    int bh = blockIdx.y, n0 = blockIdx.x * 128;
    int b = bh >> 3, h = bh & 7;
    int tid = threadIdx.x;
    if (tid < 33) sw[tid] = res_w[h * 33 + tid];
    const float* vb = g_v + (size_t)bh * NN * DH;
    #pragma unroll
    for (int i = 0; i < 10; i++) {
        int idx = tid + i * 256;
        int r = idx >> 4, c4 = idx & 15;
        int tok = n0 - 16 + r;
        float4 val = make_float4(0.f, 0.f, 0.f, 0.f);
        if (tok >= 0 && tok < NN)
            val = *(const float4*)(vb + (size_t)tok * DH + c4 * 4);
        *(float4*)&sv[r][c4 * 4] = val;
    }
    __syncthreads();
    #pragma unroll
    for (int i = 0; i < 8; i++) {
        int idx = tid + i * 256;
        int nl = idx >> 4, dg = idx & 15;
        float4 acc = make_float4(0.f, 0.f, 0.f, 0.f);
        #pragma unroll
        for (int j = 0; j < 33; j++) {
            float w = sw[j];
            float4 vv = *(const float4*)&sv[nl + j][dg * 4];
            acc.x += w * vv.x; acc.y += w * vv.y;
            acc.z += w * vv.z; acc.w += w * vv.w;
        }
        *(float4*)(g_y + ((size_t)b * NN + n0 + nl) * DD + h * 64 + dg * 4) = acc;
    }
}

// ---------------------------------------------------------------------------
// Launch
// ---------------------------------------------------------------------------
extern "C" void kernel_launch(void* const* d_in, const int* in_sizes, int n_in,
                              void* d_out, int out_size) {
    const float* x     = (const float*)d_in[0];
    const float* ln_w  = (const float*)d_in[1];
    const float* ln_b  = (const float*)d_in[2];
    const float* w_qkv = (const float*)d_in[3];
    const float* w_out = (const float*)d_in[4];
    const float* b_out = (const float*)d_in[5];
    const float* res_w = (const float*)d_in[6];
    float* out = (float*)d_out;

    float *p_xn, *p_q, *p_k, *p_v, *p_ql, *p_kl, *p_attn2;
    float *p_z, *p_z2, *p_xz, *p_t, *p_u;
    float *p_p3, *p_out3, *p_wc, *p_y;
    void *p_h3, *p_h1;
    cudaGetSymbolAddress((void**)&p_xn, g_xn);
    cudaGetSymbolAddress((void**)&p_q,  g_q);
    cudaGetSymbolAddress((void**)&p_k,  g_k);
    cudaGetSymbolAddress((void**)&p_v,  g_v);
    cudaGetSymbolAddress((void**)&p_ql, g_ql);
    cudaGetSymbolAddress((void**)&p_kl, g_kl);
    cudaGetSymbolAddress((void**)&p_attn2, g_attn2);
    cudaGetSymbolAddress((void**)&p_z,  g_z);
    cudaGetSymbolAddress((void**)&p_z2, g_z2);
    cudaGetSymbolAddress((void**)&p_xz, g_xz);
    cudaGetSymbolAddress((void**)&p_t,  g_t);
    cudaGetSymbolAddress((void**)&p_u,  g_u);
    cudaGetSymbolAddress(&p_h3, g_h3);
    cudaGetSymbolAddress(&p_h1, g_h1);
    cudaGetSymbolAddress((void**)&p_p3, g_p3);
    cudaGetSymbolAddress((void**)&p_out3, g_out3);
    cudaGetSymbolAddress((void**)&p_wc, g_wc);
    cudaGetSymbolAddress((void**)&p_y,  g_y);

    // LN -> QKV (bf16) -> landmarks
    ln_kernel<<<BB * NN, 128>>>(x, ln_w, ln_b);
    bf_gemm<0,128,128,32,false,false><<<dim3(12, 256, 1), 256>>>(
        p_xn, w_qkv, nullptr, nullptr, nullptr,
        1536, 512, 512, 1536, 0, 0, 0);
    landmark_kernel<<<dim3(MM, BH), 64>>>();

    // sim2 (fp32); sim3 -> bf16 scores; sim1 fused softmax -> bf16 probs
    gemm_sim2<<<dim3(2, 2, BH), 256>>>();
    bf_gemm<6,128,128,32,true,false><<<dim3(64, 2, BH), 256>>>(
        p_ql, p_k, p_h3, nullptr, nullptr,
        NN, 64, 64, 64, (long long)MM*DH, (long long)NN*DH, (long long)MM*NN);
    sim1_fused<<<dim3(1, 128, BH), 256>>>();

    // softmaxes
    softmax256<<<BH * MM, 256>>>();        // attn2 (f32)
    softmax8192bf<<<BH * MM, 256>>>();     // attn3 (bf16 in place)

    // pinv
    init_max_kernel<<<1, 1>>>();
    colrowmax_kernel<<<BH, 256>>>();
    z0_kernel<<<dim3(8, 8, BH), 256>>>();

    dim3 gba(2, 2, BH);
    float *zc = p_z, *zn = p_z2;
    for (int it = 0; it < 5; it++) {   // iterations 0..4 in tf32
        tc_gemm<4,128,128,32,false><<<gba, 256>>>(p_attn2, zc, p_xz, nullptr,
            MM, 256, 256, 256, (long long)MM*MM, (long long)MM*MM, (long long)MM*MM, 1.f, 0.f);
        tc_gemm<4,128,128,32,false><<<gba, 256>>>(p_xz, p_xz, p_t, p_xz,
            MM, 256, 256, 256, (long long)MM*MM, (long long)MM*MM, (long long)MM*MM, -1.f, 7.f);
        tc_gemm<4,128,128,32,false><<<gba, 256>>>(p_xz, p_t, p_u, p_xz,
            MM, 256, 256, 256, (long long)MM*MM, (long long)MM*MM, (long long)MM*MM, -1.f, 15.f);
        tc_gemm<4,128,128,32,false><<<gba, 256>>>(zc, p_u, zn, zc,
            MM, 256, 256, 256, (long long)MM*MM, (long long)MM*MM, (long long)MM*MM, -0.25f, 3.25f);
        float* tmp = zc; zc = zn; zn = tmp;
    }
    // final iteration in fp32 FFMA
    matmul_ba128<<<gba, 256>>>(p_attn2, zc, nullptr, p_xz, 1.f, 0.f);
    matmul_ba128<<<gba, 256>>>(p_xz, p_xz, p_xz, p_t, -1.f, 7.f);
    matmul_ba128<<<gba, 256>>>(p_xz, p_t, p_xz, p_u, -1.f, 15.f);
    matmul_ba128<<<gba, 256>>>(zc, p_u, zc, zn, -0.25f, 3.25f);
    { float* tmp = zc; zc = zn; zn = tmp; }

    // out3 = attn3 @ v (bf16 A, k-split 16) then reduce
    bf_gemm<3,128,64,32,false,true><<<dim3(1, 2, BH * KS), 256>>>(
        p_h3, p_v, p_p3, nullptr, nullptr,
        64, 512, NN, 64, 0, 0, 0);
    reduce_p3<<<2048, 256>>>();

    // Wc = z_final @ out3 (tf32)
    tc_gemm<2,128,64,32,false><<<dim3(1, 2, BH), 256>>>(
        zc, p_out3, p_wc, nullptr,
        64, 256, 256, 64, (long long)MM*MM, (long long)MM*DH, (long long)MM*DH, 0.f, 0.f);

    // y = conv residual ; y += attn1 @ Wc (bf16 A)
    conv_kernel<<<dim3(64, BH), 256>>>(res_w);
    bf_gemm<5,128,64,32,false,true><<<dim3(1, 64, BH), 256>>>(
        p_h1, p_wc, p_y, nullptr, nullptr,
        64, 256, 256, 64, (long long)NN*MM, (long long)MM*DH, 0);

    // out = y @ w_out + b_out + x (bf16)
    bf_gemm<1,128,128,32,false,false><<<dim3(4, 256, 1), 256>>>(
        p_y, w_out, out, b_out, x,
        512, 512, 512, 512, 0, 0, 0);
}